// round 12
// baseline (speedup 1.0000x reference)
#include <cuda_runtime.h>
#include <cuda_fp16.h>
#include <math.h>

#define N_NODES 20000
#define D 8
#define DP1 9
#define M_ROWS (N_NODES * DP1)   // 180000
#define IN_F 64
#define HID 128
#define OUT_F 64
#define NE 100000
#define EPS 1e-5f
#define SPAD 64
#define CAP 96

// ---------------- scratch ----------------
__device__ __half g_y1h[N_NODES * HID];       // x @ W1, fp16 (5.12 MB)
__device__ __half g_pre1h[M_ROWS * HID];      // fp16 pre1 (46 MB)
__device__ float  g_pre2[N_NODES * OUT_F];
__device__ float  g_embs[N_NODES * OUT_F];    // relu(bn2(pre2))
__device__ float  g_embw[N_NODES * OUT_F];    // embs * Wd
__device__ float  g_sts[N_NODES * D];         // per-node ts-sorted neighbor ts
__device__ int    g_sgi[N_NODES * D];         // per-node ts-sorted neighbor idx
__device__ int    g_cnt[N_NODES];
__device__ float  g_bq[N_NODES * CAP];
__device__ int    g_bm[N_NODES * CAP];
__device__ float  g_s1[HID * SPAD],  g_q1[HID * SPAD];
__device__ float  g_s2[OUT_F * SPAD], g_q2[OUT_F * SPAD];
__device__ double g_loss;
__device__ int    g_done;

// ---------------- K0: zero accumulators + sort each node's neighbors by ts ----------------
__global__ void k_zero(const int* __restrict__ nbi, const float* __restrict__ nbt) {
    const int t = blockIdx.x * blockDim.x + threadIdx.x;
    if (blockIdx.x == 0) {
        const int tid = threadIdx.x;
        if (tid < HID)   { g_s1[tid * SPAD] = 0.f; g_q1[tid * SPAD] = 0.f; }
        if (tid < OUT_F) { g_s2[tid * SPAD] = 0.f; g_q2[tid * SPAD] = 0.f; }
        if (tid == 0)    { g_loss = 0.0; g_done = 0; }
    }
    if (t >= N_NODES) return;
    g_cnt[t] = 0;
    float ts[D]; int gi[D];
    const float4 t0 = __ldg((const float4*)&nbt[t * D]);
    const float4 t1 = __ldg((const float4*)&nbt[t * D + 4]);
    const int4   i0 = __ldg((const int4*)&nbi[t * D]);
    const int4   i1 = __ldg((const int4*)&nbi[t * D + 4]);
    ts[0]=t0.x; ts[1]=t0.y; ts[2]=t0.z; ts[3]=t0.w;
    ts[4]=t1.x; ts[5]=t1.y; ts[6]=t1.z; ts[7]=t1.w;
    gi[0]=i0.x; gi[1]=i0.y; gi[2]=i0.z; gi[3]=i0.w;
    gi[4]=i1.x; gi[5]=i1.y; gi[6]=i1.z; gi[7]=i1.w;
    // Batcher odd-even merge sort, 19 branchless compare-exchanges
#define CE(a, b) { bool p = ts[a] > ts[b]; \
    float tA = ts[a], tB = ts[b]; ts[a] = p ? tB : tA; ts[b] = p ? tA : tB; \
    int   iA = gi[a], iB = gi[b]; gi[a] = p ? iB : iA; gi[b] = p ? iA : iB; }
    CE(0,1) CE(2,3) CE(4,5) CE(6,7)
    CE(0,2) CE(1,3) CE(4,6) CE(5,7)
    CE(1,2) CE(5,6)
    CE(0,4) CE(1,5) CE(2,6) CE(3,7)
    CE(2,4) CE(3,5)
    CE(1,2) CE(3,4) CE(5,6)
#undef CE
    *(float4*)&g_sts[t * D]     = make_float4(ts[0], ts[1], ts[2], ts[3]);
    *(float4*)&g_sts[t * D + 4] = make_float4(ts[4], ts[5], ts[6], ts[7]);
    *(int4*)&g_sgi[t * D]       = make_int4(gi[0], gi[1], gi[2], gi[3]);
    *(int4*)&g_sgi[t * D + 4]   = make_int4(gi[4], gi[5], gi[6], gi[7]);
}

// ---------------- K1: y1 = x @ W1 (fp16 output) ----------------
__global__ void k_gemm1(const float* __restrict__ x, const float* __restrict__ W1) {
    __shared__ float sX[32 * IN_F];
    __shared__ float sW[IN_F * HID];
    const int tid  = threadIdx.x;
    const int row0 = blockIdx.x * 32;
    for (int i = tid; i < 32 * IN_F; i += 128) sX[i] = x[(size_t)row0 * IN_F + i];
    for (int i = tid; i < IN_F * HID; i += 128) sW[i] = W1[i];
    __syncthreads();
    const int tr = tid >> 5;
    const int tc = tid & 31;
    float acc[8][4];
#pragma unroll
    for (int r = 0; r < 8; r++)
#pragma unroll
        for (int c = 0; c < 4; c++) acc[r][c] = 0.f;
#pragma unroll 8
    for (int f = 0; f < IN_F; f++) {
        const float4 w = *(const float4*)&sW[f * HID + tc * 4];
#pragma unroll
        for (int r = 0; r < 8; r++) {
            const float a = sX[(tr * 8 + r) * IN_F + f];
            acc[r][0] = fmaf(a, w.x, acc[r][0]);
            acc[r][1] = fmaf(a, w.y, acc[r][1]);
            acc[r][2] = fmaf(a, w.z, acc[r][2]);
            acc[r][3] = fmaf(a, w.w, acc[r][3]);
        }
    }
#pragma unroll
    for (int r = 0; r < 8; r++) {
        union { __half2 h[2]; uint2 u; } pk;
        pk.h[0] = __floats2half2_rn(acc[r][0], acc[r][1]);
        pk.h[1] = __floats2half2_rn(acc[r][2], acc[r][3]);
        *(uint2*)&g_y1h[(size_t)(row0 + tr * 8 + r) * HID + tc * 4] = pk.u;
    }
}

// ---------------- K2: scatter queries into per-child buckets ----------------
__global__ void k_build(const float* __restrict__ node_ts,
                        const int*   __restrict__ nbi,
                        const float* __restrict__ nbt) {
    const int q = blockIdx.x * blockDim.x + threadIdx.x;
    if (q >= M_ROWS) return;
    const int i = q / DP1;
    const int j = q - i * DP1;
    const float ts_i = __ldg(&node_ts[i]);
    int ci; float cts;
    if (j < D) { ci = __ldg(&nbi[i * D + j]); cts = __ldg(&nbt[i * D + j]); }
    else       { ci = i;                      cts = ts_i; }
    const bool valid = (cts <= ts_i);
    const int slot = atomicAdd(&g_cnt[ci], 1);
    if (slot < CAP) {
        g_bq[ci * CAP + slot] = cts;
        g_bm[ci * CAP + slot] = valid ? q : (q | 0x80000000);
    }
}

// ---------------- K3: per-child worker — smem prefix sums, LDS per query ----------------
__global__ void k_child(const float* __restrict__ b1) {
    __shared__ float sS[HID];
    __shared__ float sQ[HID];
    __shared__ uint2 sPre[8 * DP1 * 32];   // 18 KB: per-warp 9 prefix rows x 32 lanes
    const int tid  = threadIdx.x;
    const int w    = tid >> 5, lane = tid & 31;
    if (tid < HID)            sS[tid] = 0.f;
    else if (tid < 2 * HID)   sQ[tid - HID] = 0.f;
    __syncthreads();
    const int c = blockIdx.x * 8 + w;

    float ts[D]; int gi[D];
    {
        const float4 t0 = __ldg((const float4*)&g_sts[c * D]);
        const float4 t1 = __ldg((const float4*)&g_sts[c * D + 4]);
        const int4   i0 = __ldg((const int4*)&g_sgi[c * D]);
        const int4   i1 = __ldg((const int4*)&g_sgi[c * D + 4]);
        ts[0]=t0.x; ts[1]=t0.y; ts[2]=t0.z; ts[3]=t0.w;
        ts[4]=t1.x; ts[5]=t1.y; ts[6]=t1.z; ts[7]=t1.w;
        gi[0]=i0.x; gi[1]=i0.y; gi[2]=i0.z; gi[3]=i0.w;
        gi[4]=i1.x; gi[5]=i1.y; gi[6]=i1.z; gi[7]=i1.w;
    }

    union U2 { __half2 h[2]; uint2 u; };
    uint2* myPre = &sPre[w * DP1 * 32];
    // prefix sums over sorted rows (P[0] = self, P[k] = P[k-1] + row_sorted[k-1])
    {
        U2 p; p.u = *(const uint2*)&g_y1h[(size_t)c * HID + lane * 4];
        myPre[lane] = p.u;
#pragma unroll
        for (int k = 0; k < D; k++) {
            U2 r; r.u = *(const uint2*)&g_y1h[(size_t)gi[k] * HID + lane * 4];
            p.h[0] = __hadd2(p.h[0], r.h[0]);
            p.h[1] = __hadd2(p.h[1], r.h[1]);
            myPre[(k + 1) * 32 + lane] = p.u;
        }
    }
    const float4 bb = *(const float4*)&b1[lane * 4];

    const int n = min(g_cnt[c], CAP);
    float4 ps = make_float4(0.f, 0.f, 0.f, 0.f);
    float4 pq = make_float4(0.f, 0.f, 0.f, 0.f);
#pragma unroll 2
    for (int s = 0; s < n; s++) {
        const float cts = g_bq[c * CAP + s];      // warp-uniform
        const int   me  = g_bm[c * CAP + s];
        int idx = 0;
#pragma unroll
        for (int k = 0; k < D; k++) idx += (ts[k] <= cts) ? 1 : 0;
        U2 pv; pv.u = myPre[idx * 32 + lane];     // warp-uniform idx -> no conflicts
        const float inv = __fdividef(1.f, (float)(idx + 1));
        const float2 f0 = __half22float2(pv.h[0]);
        const float2 f1 = __half22float2(pv.h[1]);
        float4 o;
        o.x = fmaf(f0.x, inv, bb.x);
        o.y = fmaf(f0.y, inv, bb.y);
        o.z = fmaf(f1.x, inv, bb.z);
        o.w = fmaf(f1.y, inv, bb.w);
        ps.x += o.x; ps.y += o.y; ps.z += o.z; ps.w += o.w;
        pq.x += o.x * o.x; pq.y += o.y * o.y; pq.z += o.z * o.z; pq.w += o.w * o.w;
        if (me >= 0) {
            U2 pk;
            pk.h[0] = __floats2half2_rn(o.x, o.y);
            pk.h[1] = __floats2half2_rn(o.z, o.w);
            *(uint2*)&g_pre1h[(size_t)me * HID + lane * 4] = pk.u;
        }
    }
    atomicAdd(&sS[lane * 4 + 0], ps.x);
    atomicAdd(&sS[lane * 4 + 1], ps.y);
    atomicAdd(&sS[lane * 4 + 2], ps.z);
    atomicAdd(&sS[lane * 4 + 3], ps.w);
    atomicAdd(&sQ[lane * 4 + 0], pq.x);
    atomicAdd(&sQ[lane * 4 + 1], pq.y);
    atomicAdd(&sQ[lane * 4 + 2], pq.z);
    atomicAdd(&sQ[lane * 4 + 3], pq.w);
    __syncthreads();
    if (tid < HID) {
        atomicAdd(&g_s1[tid * SPAD], sS[tid]);
        atomicAdd(&g_q1[tid * SPAD], sQ[tid]);
    }
}

// ---------------- K4: fused BN1+ReLU masked-mean -> gemm2 + BN2 partials ----------------
__global__ void k_bngemm2(const float* __restrict__ node_ts,
                          const float* __restrict__ nbt,
                          const float* __restrict__ g1, const float* __restrict__ be1,
                          const float* __restrict__ W2, const float* __restrict__ b2) {
    __shared__ float sA[32 * HID];      // 16 KB
    __shared__ float sW[HID * OUT_F];   // 32 KB
    __shared__ float sSc[HID], sSh[HID];
    __shared__ float sS[OUT_F], sQ[OUT_F];
    const int tid  = threadIdx.x;
    const int w    = tid >> 5, lane = tid & 31;
    const int row0 = blockIdx.x * 32;
    for (int i = tid; i < HID * OUT_F; i += 256) sW[i] = W2[i];
    if (tid < HID) {
        const float mean = g_s1[tid * SPAD] * (1.f / (float)M_ROWS);
        const float var  = g_q1[tid * SPAD] * (1.f / (float)M_ROWS) - mean * mean;
        const float sc   = __ldg(&g1[tid]) * rsqrtf(fmaxf(var, 0.f) + EPS);
        sSc[tid] = sc;
        sSh[tid] = __ldg(&be1[tid]) - mean * sc;
    }
    if (tid < OUT_F) { sS[tid] = 0.f; sQ[tid] = 0.f; }
    __syncthreads();
    const float4 sc4 = *(const float4*)&sSc[lane * 4];
    const float4 sh4 = *(const float4*)&sSh[lane * 4];
#pragma unroll
    for (int half = 0; half < 2; half++) {
        const int iA = row0 + w * 4 + half * 2;
        const int iB = iA + 1;
        const float tsA = __ldg(&node_ts[iA]);
        const float tsB = __ldg(&node_ts[iB]);
        bool valA[D], valB[D];
        float cntA = 1.f, cntB = 1.f;
#pragma unroll
        for (int j = 0; j < D; j++) {
            valA[j] = (__ldg(&nbt[iA * D + j]) <= tsA);
            valB[j] = (__ldg(&nbt[iB * D + j]) <= tsB);
            cntA += valA[j] ? 1.f : 0.f;
            cntB += valB[j] ? 1.f : 0.f;
        }
        uint2 rA[DP1], rB[DP1];
#pragma unroll
        for (int j = 0; j < DP1; j++) {
            rA[j] = *(const uint2*)&g_pre1h[(size_t)(iA * DP1 + j) * HID + lane * 4];
            rB[j] = *(const uint2*)&g_pre1h[(size_t)(iB * DP1 + j) * HID + lane * 4];
        }
        {
            float2 f0 = __half22float2(*(__half2*)&rA[D].x);
            float2 f1 = __half22float2(*(__half2*)&rA[D].y);
            float4 acc;
            acc.x = fmaxf(fmaf(f0.x, sc4.x, sh4.x), 0.f);
            acc.y = fmaxf(fmaf(f0.y, sc4.y, sh4.y), 0.f);
            acc.z = fmaxf(fmaf(f1.x, sc4.z, sh4.z), 0.f);
            acc.w = fmaxf(fmaf(f1.y, sc4.w, sh4.w), 0.f);
#pragma unroll
            for (int j = 0; j < D; j++) {
                float2 a0 = __half22float2(*(__half2*)&rA[j].x);
                float2 a1 = __half22float2(*(__half2*)&rA[j].y);
                acc.x += valA[j] ? fmaxf(fmaf(a0.x, sc4.x, sh4.x), 0.f) : 0.f;
                acc.y += valA[j] ? fmaxf(fmaf(a0.y, sc4.y, sh4.y), 0.f) : 0.f;
                acc.z += valA[j] ? fmaxf(fmaf(a1.x, sc4.z, sh4.z), 0.f) : 0.f;
                acc.w += valA[j] ? fmaxf(fmaf(a1.y, sc4.w, sh4.w), 0.f) : 0.f;
            }
            const float inv = 1.f / cntA;
            *(float4*)&sA[(w * 4 + half * 2) * HID + lane * 4] =
                make_float4(acc.x * inv, acc.y * inv, acc.z * inv, acc.w * inv);
        }
        {
            float2 f0 = __half22float2(*(__half2*)&rB[D].x);
            float2 f1 = __half22float2(*(__half2*)&rB[D].y);
            float4 acc;
            acc.x = fmaxf(fmaf(f0.x, sc4.x, sh4.x), 0.f);
            acc.y = fmaxf(fmaf(f0.y, sc4.y, sh4.y), 0.f);
            acc.z = fmaxf(fmaf(f1.x, sc4.z, sh4.z), 0.f);
            acc.w = fmaxf(fmaf(f1.y, sc4.w, sh4.w), 0.f);
#pragma unroll
            for (int j = 0; j < D; j++) {
                float2 a0 = __half22float2(*(__half2*)&rB[j].x);
                float2 a1 = __half22float2(*(__half2*)&rB[j].y);
                acc.x += valB[j] ? fmaxf(fmaf(a0.x, sc4.x, sh4.x), 0.f) : 0.f;
                acc.y += valB[j] ? fmaxf(fmaf(a0.y, sc4.y, sh4.y), 0.f) : 0.f;
                acc.z += valB[j] ? fmaxf(fmaf(a1.x, sc4.z, sh4.z), 0.f) : 0.f;
                acc.w += valB[j] ? fmaxf(fmaf(a1.y, sc4.w, sh4.w), 0.f) : 0.f;
            }
            const float inv = 1.f / cntB;
            *(float4*)&sA[(w * 4 + half * 2 + 1) * HID + lane * 4] =
                make_float4(acc.x * inv, acc.y * inv, acc.z * inv, acc.w * inv);
        }
    }
    __syncthreads();
    const int tr = tid >> 4;
    const int tc = tid & 15;
    float acc[2][4];
#pragma unroll
    for (int r = 0; r < 2; r++)
#pragma unroll
        for (int cc = 0; cc < 4; cc++) acc[r][cc] = 0.f;
#pragma unroll 8
    for (int f = 0; f < HID; f++) {
        const float4 wv = *(const float4*)&sW[f * OUT_F + tc * 4];
#pragma unroll
        for (int r = 0; r < 2; r++) {
            const float a = sA[(tr * 2 + r) * HID + f];
            acc[r][0] = fmaf(a, wv.x, acc[r][0]);
            acc[r][1] = fmaf(a, wv.y, acc[r][1]);
            acc[r][2] = fmaf(a, wv.z, acc[r][2]);
            acc[r][3] = fmaf(a, wv.w, acc[r][3]);
        }
    }
    const float4 bbv = *(const float4*)&b2[tc * 4];
    float ps[4] = {0.f, 0.f, 0.f, 0.f}, pq[4] = {0.f, 0.f, 0.f, 0.f};
#pragma unroll
    for (int r = 0; r < 2; r++) {
        float4 o = make_float4(acc[r][0] + bbv.x, acc[r][1] + bbv.y,
                               acc[r][2] + bbv.z, acc[r][3] + bbv.w);
        *(float4*)&g_pre2[(size_t)(row0 + tr * 2 + r) * OUT_F + tc * 4] = o;
        ps[0] += o.x; ps[1] += o.y; ps[2] += o.z; ps[3] += o.w;
        pq[0] += o.x * o.x; pq[1] += o.y * o.y; pq[2] += o.z * o.z; pq[3] += o.w * o.w;
    }
#pragma unroll
    for (int cc = 0; cc < 4; cc++) {
        atomicAdd(&sS[tc * 4 + cc], ps[cc]);
        atomicAdd(&sQ[tc * 4 + cc], pq[cc]);
    }
    __syncthreads();
    if (tid < OUT_F) {
        atomicAdd(&g_s2[tid * SPAD], sS[tid]);
        atomicAdd(&g_q2[tid * SPAD], sQ[tid]);
    }
}

// ---------------- K5: embs = relu(bn2(pre2)); embw = embs * Wd ----------------
__global__ void k_embs(const float* __restrict__ g2, const float* __restrict__ be2,
                       const float* __restrict__ Wd) {
    __shared__ float sSc[OUT_F], sSh[OUT_F], sWd[OUT_F];
    const int tid = threadIdx.x;
    if (tid < OUT_F) {
        const float mean = g_s2[tid * SPAD] * (1.f / (float)N_NODES);
        const float var  = g_q2[tid * SPAD] * (1.f / (float)N_NODES) - mean * mean;
        const float sc   = __ldg(&g2[tid]) * rsqrtf(fmaxf(var, 0.f) + EPS);
        sSc[tid] = sc;
        sSh[tid] = __ldg(&be2[tid]) - mean * sc;
        sWd[tid] = __ldg(&Wd[tid]);
    }
    __syncthreads();
    const int idx = blockIdx.x * blockDim.x + tid;    // over float4s
    if (idx < N_NODES * OUT_F / 4) {
        const int c0 = (idx & 15) * 4;
        float4 v = *(const float4*)&g_pre2[(size_t)idx * 4];
        float4 e;
        e.x = fmaxf(fmaf(v.x, sSc[c0 + 0], sSh[c0 + 0]), 0.f);
        e.y = fmaxf(fmaf(v.y, sSc[c0 + 1], sSh[c0 + 1]), 0.f);
        e.z = fmaxf(fmaf(v.z, sSc[c0 + 2], sSh[c0 + 2]), 0.f);
        e.w = fmaxf(fmaf(v.w, sSc[c0 + 3], sSh[c0 + 3]), 0.f);
        *(float4*)&g_embs[(size_t)idx * 4] = e;
        float4 ew;
        ew.x = e.x * sWd[c0 + 0];
        ew.y = e.y * sWd[c0 + 1];
        ew.z = e.z * sWd[c0 + 2];
        ew.w = e.w * sWd[c0 + 3];
        *(float4*)&g_embw[(size_t)idx * 4] = ew;
    }
}

// ---------------- K6: decoder + BCE (plain dot of embw[a], embs[b]) ----------------
__global__ void k_loss(const int* __restrict__ target, const int* __restrict__ neg,
                       const float* __restrict__ bd, float* __restrict__ out) {
    __shared__ double sAcc[8];
    const int tid = threadIdx.x, w = tid >> 5, lane = tid & 31;
    const int grp = lane >> 3, hl = lane & 7;
    const float bdv = __ldg(&bd[0]);
    double acc = 0.0;
    const int p0 = blockIdx.x * 256;
    for (int it = 0; it < 8; it++) {
        const int p = p0 + it * 32 + w * 4 + grp;
        float d = 0.f; float label = 0.f; bool live = (p < 2 * NE);
        if (live) {
            int a, b;
            if (p < NE) { a = __ldg(&target[p]);   b = __ldg(&target[NE + p]); label = 1.f; }
            else        { a = __ldg(&neg[p - NE]); b = __ldg(&neg[p]);         label = 0.f; }
            const float4 va0 = *(const float4*)&g_embw[(size_t)a * OUT_F + hl * 8];
            const float4 va1 = *(const float4*)&g_embw[(size_t)a * OUT_F + hl * 8 + 4];
            const float4 vb0 = *(const float4*)&g_embs[(size_t)b * OUT_F + hl * 8];
            const float4 vb1 = *(const float4*)&g_embs[(size_t)b * OUT_F + hl * 8 + 4];
            d = va0.x * vb0.x;
            d = fmaf(va0.y, vb0.y, d);
            d = fmaf(va0.z, vb0.z, d);
            d = fmaf(va0.w, vb0.w, d);
            d = fmaf(va1.x, vb1.x, d);
            d = fmaf(va1.y, vb1.y, d);
            d = fmaf(va1.z, vb1.z, d);
            d = fmaf(va1.w, vb1.w, d);
        }
#pragma unroll
        for (int off = 4; off; off >>= 1) d += __shfl_xor_sync(0xffffffff, d, off);
        if (hl == 0 && live) {
            const float pl   = d + bdv;
            const float term = fmaxf(pl, 0.f) - pl * label + log1pf(__expf(-fabsf(pl)));
            acc += (double)term;
        }
    }
    acc += __shfl_xor_sync(0xffffffff, acc, 8);
    acc += __shfl_xor_sync(0xffffffff, acc, 16);
    if (lane == 0) sAcc[w] = acc;
    __syncthreads();
    if (tid == 0) {
        double s = 0.0;
#pragma unroll
        for (int k = 0; k < 8; k++) s += sAcc[k];
        atomicAdd(&g_loss, s);
        __threadfence();
        const int dn = atomicAdd(&g_done, 1);
        if (dn == (int)gridDim.x - 1)
            out[0] = (float)(g_loss * (1.0 / (2.0 * (double)NE)));
    }
}

// ---------------- launch ----------------
extern "C" void kernel_launch(void* const* d_in, const int* in_sizes, int n_in,
                              void* d_out, int out_size) {
    const float* x       = (const float*)d_in[0];
    const float* node_ts = (const float*)d_in[1];
    const int*   nbi     = (const int*)  d_in[2];
    const float* nbt     = (const float*)d_in[3];
    const int*   target  = (const int*)  d_in[4];
    const int*   neg     = (const int*)  d_in[5];
    const float* W1      = (const float*)d_in[6];
    const float* b1      = (const float*)d_in[7];
    const float* g1      = (const float*)d_in[8];
    const float* be1     = (const float*)d_in[9];
    const float* W2      = (const float*)d_in[10];
    const float* b2      = (const float*)d_in[11];
    const float* g2      = (const float*)d_in[12];
    const float* be2     = (const float*)d_in[13];
    const float* Wd      = (const float*)d_in[14];
    const float* bd      = (const float*)d_in[15];
    float* out = (float*)d_out;

    k_zero   <<<(N_NODES + 255) / 256, 256>>>(nbi, nbt);
    k_gemm1  <<<N_NODES / 32, 128>>>(x, W1);
    k_build  <<<(M_ROWS + 255) / 256, 256>>>(node_ts, nbi, nbt);
    k_child  <<<N_NODES / 8, 256>>>(b1);                          // <- profiled (4th)
    k_bngemm2<<<N_NODES / 32, 256>>>(node_ts, nbt, g1, be1, W2, b2);
    k_embs   <<<(N_NODES * OUT_F / 4 + 255) / 256, 256>>>(g2, be2, Wd);
    k_loss   <<<(2 * NE + 255) / 256, 256>>>(target, neg, bd, out);
}

// round 14
// speedup vs baseline: 1.0592x; 1.0592x over previous
#include <cuda_runtime.h>
#include <cuda_fp16.h>
#include <math.h>

#define N_NODES 20000
#define D 8
#define DP1 9
#define M_ROWS (N_NODES * DP1)   // 180000
#define IN_F 64
#define HID 128
#define OUT_F 64
#define NE 100000
#define EPS 1e-5f
#define SPAD 64

// ---------------- scratch ----------------
__device__ __half g_y1h[N_NODES * HID];       // x @ W1, fp16 (5.12 MB)
__device__ __half g_prefh[M_ROWS * HID];      // fp16 prefix rows (46 MB)
__device__ float  g_pre2[N_NODES * OUT_F];
__device__ float  g_sts[N_NODES * D];         // per-node ts-sorted neighbor ts
__device__ int    g_sgi[N_NODES * D];         // per-node ts-sorted neighbor idx
__device__ int    g_w[M_ROWS];                // multiplicity of (child, idx)
__device__ int    g_qkey[M_ROWS];             // (row<<4)|idx, ~x if mask2-invalid
__device__ float  g_s1[HID * SPAD],  g_q1[HID * SPAD];
__device__ float  g_s2[OUT_F * SPAD], g_q2[OUT_F * SPAD];
__device__ double g_loss;
__device__ int    g_done;

// ---------------- K0: zero accumulators + sort each node's neighbors by ts ----------------
__global__ void k_zero(const int* __restrict__ nbi, const float* __restrict__ nbt) {
    const int t = blockIdx.x * blockDim.x + threadIdx.x;
    if (blockIdx.x == 0) {
        const int tid = threadIdx.x;
        if (tid < HID)   { g_s1[tid * SPAD] = 0.f; g_q1[tid * SPAD] = 0.f; }
        if (tid < OUT_F) { g_s2[tid * SPAD] = 0.f; g_q2[tid * SPAD] = 0.f; }
        if (tid == 0)    { g_loss = 0.0; g_done = 0; }
    }
    if (t >= N_NODES) return;
#pragma unroll
    for (int k = 0; k < DP1; k++) g_w[t * DP1 + k] = 0;
    float ts[D]; int gi[D];
    const float4 t0 = __ldg((const float4*)&nbt[t * D]);
    const float4 t1 = __ldg((const float4*)&nbt[t * D + 4]);
    const int4   i0 = __ldg((const int4*)&nbi[t * D]);
    const int4   i1 = __ldg((const int4*)&nbi[t * D + 4]);
    ts[0]=t0.x; ts[1]=t0.y; ts[2]=t0.z; ts[3]=t0.w;
    ts[4]=t1.x; ts[5]=t1.y; ts[6]=t1.z; ts[7]=t1.w;
    gi[0]=i0.x; gi[1]=i0.y; gi[2]=i0.z; gi[3]=i0.w;
    gi[4]=i1.x; gi[5]=i1.y; gi[6]=i1.z; gi[7]=i1.w;
#define CE(a, b) { bool p = ts[a] > ts[b]; \
    float tA = ts[a], tB = ts[b]; ts[a] = p ? tB : tA; ts[b] = p ? tA : tB; \
    int   iA = gi[a], iB = gi[b]; gi[a] = p ? iB : iA; gi[b] = p ? iA : iB; }
    CE(0,1) CE(2,3) CE(4,5) CE(6,7)
    CE(0,2) CE(1,3) CE(4,6) CE(5,7)
    CE(1,2) CE(5,6)
    CE(0,4) CE(1,5) CE(2,6) CE(3,7)
    CE(2,4) CE(3,5)
    CE(1,2) CE(3,4) CE(5,6)
#undef CE
    *(float4*)&g_sts[t * D]     = make_float4(ts[0], ts[1], ts[2], ts[3]);
    *(float4*)&g_sts[t * D + 4] = make_float4(ts[4], ts[5], ts[6], ts[7]);
    *(int4*)&g_sgi[t * D]       = make_int4(gi[0], gi[1], gi[2], gi[3]);
    *(int4*)&g_sgi[t * D + 4]   = make_int4(gi[4], gi[5], gi[6], gi[7]);
}

// ---------------- K1: y1 = x @ W1 (fp16 output) ----------------
__global__ void k_gemm1(const float* __restrict__ x, const float* __restrict__ W1) {
    __shared__ float sX[32 * IN_F];
    __shared__ float sW[IN_F * HID];
    const int tid  = threadIdx.x;
    const int row0 = blockIdx.x * 32;
    for (int i = tid; i < 32 * IN_F; i += 128) sX[i] = x[(size_t)row0 * IN_F + i];
    for (int i = tid; i < IN_F * HID; i += 128) sW[i] = W1[i];
    __syncthreads();
    const int tr = tid >> 5;
    const int tc = tid & 31;
    float acc[8][4];
#pragma unroll
    for (int r = 0; r < 8; r++)
#pragma unroll
        for (int c = 0; c < 4; c++) acc[r][c] = 0.f;
#pragma unroll 8
    for (int f = 0; f < IN_F; f++) {
        const float4 w = *(const float4*)&sW[f * HID + tc * 4];
#pragma unroll
        for (int r = 0; r < 8; r++) {
            const float a = sX[(tr * 8 + r) * IN_F + f];
            acc[r][0] = fmaf(a, w.x, acc[r][0]);
            acc[r][1] = fmaf(a, w.y, acc[r][1]);
            acc[r][2] = fmaf(a, w.z, acc[r][2]);
            acc[r][3] = fmaf(a, w.w, acc[r][3]);
        }
    }
#pragma unroll
    for (int r = 0; r < 8; r++) {
        union { __half2 h[2]; uint2 u; } pk;
        pk.h[0] = __floats2half2_rn(acc[r][0], acc[r][1]);
        pk.h[1] = __floats2half2_rn(acc[r][2], acc[r][3]);
        *(uint2*)&g_y1h[(size_t)(row0 + tr * 8 + r) * HID + tc * 4] = pk.u;
    }
}

// ---------------- K2: per-query (child, idx) key + multiplicity histogram ----------------
__global__ void k_widx(const float* __restrict__ node_ts,
                       const int*   __restrict__ nbi,
                       const float* __restrict__ nbt) {
    const int q = blockIdx.x * blockDim.x + threadIdx.x;
    if (q >= M_ROWS) return;
    const int i = q / DP1;
    const int j = q - i * DP1;
    const float ts_i = __ldg(&node_ts[i]);
    int ci; float cts;
    if (j < D) { ci = __ldg(&nbi[i * D + j]); cts = __ldg(&nbt[i * D + j]); }
    else       { ci = i;                      cts = ts_i; }
    const bool valid = (cts <= ts_i);
    const float4 t0 = __ldg((const float4*)&g_sts[ci * D]);
    const float4 t1 = __ldg((const float4*)&g_sts[ci * D + 4]);
    int idx = (t0.x <= cts) + (t0.y <= cts) + (t0.z <= cts) + (t0.w <= cts)
            + (t1.x <= cts) + (t1.y <= cts) + (t1.z <= cts) + (t1.w <= cts);
    const int rowid = ci * DP1 + idx;
    atomicAdd(&g_w[rowid], 1);
    const int key = (rowid << 4) | idx;
    g_qkey[q] = valid ? key : ~key;
}

// ---------------- K3: per-node prefix rows + weighted BN1 stats -- PROFILED SLOT ----------------
// 8 warps/block, warp per node; stores only rows with w>0; stats use exact weights.
__global__ void k_pref(const float* __restrict__ b1) {
    __shared__ float sS[HID];
    __shared__ float sQ[HID];
    const int tid  = threadIdx.x;
    const int w8   = tid >> 5, lane = tid & 31;
    if (tid < HID)            sS[tid] = 0.f;
    else if (tid < 2 * HID)   sQ[tid - HID] = 0.f;
    __syncthreads();
    const int c = blockIdx.x * 8 + w8;

    int gi[D];
    {
        const int4 i0 = __ldg((const int4*)&g_sgi[c * D]);
        const int4 i1 = __ldg((const int4*)&g_sgi[c * D + 4]);
        gi[0]=i0.x; gi[1]=i0.y; gi[2]=i0.z; gi[3]=i0.w;
        gi[4]=i1.x; gi[5]=i1.y; gi[6]=i1.z; gi[7]=i1.w;
    }
    int wq[DP1];
#pragma unroll
    for (int k = 0; k < DP1; k++) wq[k] = __ldg(&g_w[c * DP1 + k]);

    union U2 { __half2 h[2]; uint2 u; };
    U2 row[D];
#pragma unroll
    for (int k = 0; k < D; k++)
        row[k].u = *(const uint2*)&g_y1h[(size_t)gi[k] * HID + lane * 4];
    U2 p; p.u = *(const uint2*)&g_y1h[(size_t)c * HID + lane * 4];

    const float4 bb = *(const float4*)&b1[lane * 4];
    float4 ps = make_float4(0.f, 0.f, 0.f, 0.f);
    float4 pq = make_float4(0.f, 0.f, 0.f, 0.f);
#pragma unroll
    for (int k = 0; k < DP1; k++) {
        if (k > 0) {
            p.h[0] = __hadd2(p.h[0], row[k - 1].h[0]);
            p.h[1] = __hadd2(p.h[1], row[k - 1].h[1]);
        }
        if (wq[k] > 0)   // warp-uniform
            *(uint2*)&g_prefh[(size_t)(c * DP1 + k) * HID + lane * 4] = p.u;
        const float wf  = (float)wq[k];
        const float inv = 1.f / (float)(k + 1);    // compile-time constant
        const float2 f0 = __half22float2(p.h[0]);
        const float2 f1 = __half22float2(p.h[1]);
        float4 v;
        v.x = fmaf(f0.x, inv, bb.x);
        v.y = fmaf(f0.y, inv, bb.y);
        v.z = fmaf(f1.x, inv, bb.z);
        v.w = fmaf(f1.y, inv, bb.w);
        ps.x += wf * v.x; ps.y += wf * v.y; ps.z += wf * v.z; ps.w += wf * v.w;
        pq.x += wf * v.x * v.x; pq.y += wf * v.y * v.y;
        pq.z += wf * v.z * v.z; pq.w += wf * v.w * v.w;
    }
    atomicAdd(&sS[lane * 4 + 0], ps.x);
    atomicAdd(&sS[lane * 4 + 1], ps.y);
    atomicAdd(&sS[lane * 4 + 2], ps.z);
    atomicAdd(&sS[lane * 4 + 3], ps.w);
    atomicAdd(&sQ[lane * 4 + 0], pq.x);
    atomicAdd(&sQ[lane * 4 + 1], pq.y);
    atomicAdd(&sQ[lane * 4 + 2], pq.z);
    atomicAdd(&sQ[lane * 4 + 3], pq.w);
    __syncthreads();
    if (tid < HID) {
        atomicAdd(&g_s1[tid * SPAD], sS[tid]);
        atomicAdd(&g_q1[tid * SPAD], sQ[tid]);
    }
}

// ---------------- K4: fused BN1+ReLU masked-mean -> gemm2 + BN2 partials ----------------
// 256 thr; 32 nodes/block; per warp 4 nodes as 2 pair-batches; rows gathered via qkey.
__global__ void k_bngemm2(const float* __restrict__ g1, const float* __restrict__ be1,
                          const float* __restrict__ b1,
                          const float* __restrict__ W2, const float* __restrict__ b2) {
    __shared__ float sA[32 * HID];      // 16 KB
    __shared__ float sW[HID * OUT_F];   // 32 KB
    __shared__ float sSc[HID], sShp[HID];
    __shared__ float sS[OUT_F], sQ[OUT_F];
    const int tid  = threadIdx.x;
    const int w    = tid >> 5, lane = tid & 31;
    const int row0 = blockIdx.x * 32;
    for (int i = tid; i < HID * OUT_F; i += 256) sW[i] = W2[i];
    if (tid < HID) {
        const float mean = g_s1[tid * SPAD] * (1.f / (float)M_ROWS);
        const float var  = g_q1[tid * SPAD] * (1.f / (float)M_ROWS) - mean * mean;
        const float sc   = __ldg(&g1[tid]) * rsqrtf(fmaxf(var, 0.f) + EPS);
        sSc[tid]  = sc;
        // fold b1 into the shift: bn(p*inv + b1) = (p*inv)*sc + (b1*sc + be1 - mean*sc)
        sShp[tid] = fmaf(__ldg(&b1[tid]) - mean, sc, __ldg(&be1[tid]));
    }
    if (tid < OUT_F) { sS[tid] = 0.f; sQ[tid] = 0.f; }
    __syncthreads();
    const float4 sc4 = *(const float4*)&sSc[lane * 4];
    const float4 sp4 = *(const float4*)&sShp[lane * 4];
#pragma unroll
    for (int half = 0; half < 2; half++) {
        const int iA = row0 + w * 4 + half * 2;
        const int iB = iA + 1;
        int keyA[DP1], keyB[DP1];
#pragma unroll
        for (int j = 0; j < DP1; j++) {
            keyA[j] = __ldg(&g_qkey[iA * DP1 + j]);
            keyB[j] = __ldg(&g_qkey[iB * DP1 + j]);
        }
        bool vA[DP1], vB[DP1];
        int rwA[DP1], rwB[DP1];
        float ivA[DP1], ivB[DP1];
        float cntA = 0.f, cntB = 0.f;
#pragma unroll
        for (int j = 0; j < DP1; j++) {
            vA[j] = keyA[j] >= 0;  int kA = vA[j] ? keyA[j] : ~keyA[j];
            vB[j] = keyB[j] >= 0;  int kB = vB[j] ? keyB[j] : ~keyB[j];
            rwA[j] = kA >> 4;      ivA[j] = __fdividef(1.f, (float)((kA & 15) + 1));
            rwB[j] = kB >> 4;      ivB[j] = __fdividef(1.f, (float)((kB & 15) + 1));
            cntA += vA[j] ? 1.f : 0.f;
            cntB += vB[j] ? 1.f : 0.f;
        }
        uint2 rA[DP1], rB[DP1];
#pragma unroll
        for (int j = 0; j < DP1; j++) {
            rA[j] = *(const uint2*)&g_prefh[(size_t)rwA[j] * HID + lane * 4];
            rB[j] = *(const uint2*)&g_prefh[(size_t)rwB[j] * HID + lane * 4];
        }
        {
            float4 acc = make_float4(0.f, 0.f, 0.f, 0.f);
#pragma unroll
            for (int j = 0; j < DP1; j++) {
                const float2 a0 = __half22float2(*(__half2*)&rA[j].x);
                const float2 a1 = __half22float2(*(__half2*)&rA[j].y);
                const float iv = ivA[j];
                acc.x += vA[j] ? fmaxf(fmaf(a0.x * iv, sc4.x, sp4.x), 0.f) : 0.f;
                acc.y += vA[j] ? fmaxf(fmaf(a0.y * iv, sc4.y, sp4.y), 0.f) : 0.f;
                acc.z += vA[j] ? fmaxf(fmaf(a1.x * iv, sc4.z, sp4.z), 0.f) : 0.f;
                acc.w += vA[j] ? fmaxf(fmaf(a1.y * iv, sc4.w, sp4.w), 0.f) : 0.f;
            }
            const float inv = __fdividef(1.f, cntA);
            *(float4*)&sA[(w * 4 + half * 2) * HID + lane * 4] =
                make_float4(acc.x * inv, acc.y * inv, acc.z * inv, acc.w * inv);
        }
        {
            float4 acc = make_float4(0.f, 0.f, 0.f, 0.f);
#pragma unroll
            for (int j = 0; j < DP1; j++) {
                const float2 a0 = __half22float2(*(__half2*)&rB[j].x);
                const float2 a1 = __half22float2(*(__half2*)&rB[j].y);
                const float iv = ivB[j];
                acc.x += vB[j] ? fmaxf(fmaf(a0.x * iv, sc4.x, sp4.x), 0.f) : 0.f;
                acc.y += vB[j] ? fmaxf(fmaf(a0.y * iv, sc4.y, sp4.y), 0.f) : 0.f;
                acc.z += vB[j] ? fmaxf(fmaf(a1.x * iv, sc4.z, sp4.z), 0.f) : 0.f;
                acc.w += vB[j] ? fmaxf(fmaf(a1.y * iv, sc4.w, sp4.w), 0.f) : 0.f;
            }
            const float inv = __fdividef(1.f, cntB);
            *(float4*)&sA[(w * 4 + half * 2 + 1) * HID + lane * 4] =
                make_float4(acc.x * inv, acc.y * inv, acc.z * inv, acc.w * inv);
        }
    }
    __syncthreads();
    const int tr = tid >> 4;
    const int tc = tid & 15;
    float acc[2][4];
#pragma unroll
    for (int r = 0; r < 2; r++)
#pragma unroll
        for (int cc = 0; cc < 4; cc++) acc[r][cc] = 0.f;
#pragma unroll 8
    for (int f = 0; f < HID; f++) {
        const float4 wv = *(const float4*)&sW[f * OUT_F + tc * 4];
#pragma unroll
        for (int r = 0; r < 2; r++) {
            const float a = sA[(tr * 2 + r) * HID + f];
            acc[r][0] = fmaf(a, wv.x, acc[r][0]);
            acc[r][1] = fmaf(a, wv.y, acc[r][1]);
            acc[r][2] = fmaf(a, wv.z, acc[r][2]);
            acc[r][3] = fmaf(a, wv.w, acc[r][3]);
        }
    }
    const float4 bbv = *(const float4*)&b2[tc * 4];
    float ps[4] = {0.f, 0.f, 0.f, 0.f}, pq[4] = {0.f, 0.f, 0.f, 0.f};
#pragma unroll
    for (int r = 0; r < 2; r++) {
        float4 o = make_float4(acc[r][0] + bbv.x, acc[r][1] + bbv.y,
                               acc[r][2] + bbv.z, acc[r][3] + bbv.w);
        *(float4*)&g_pre2[(size_t)(row0 + tr * 2 + r) * OUT_F + tc * 4] = o;
        ps[0] += o.x; ps[1] += o.y; ps[2] += o.z; ps[3] += o.w;
        pq[0] += o.x * o.x; pq[1] += o.y * o.y; pq[2] += o.z * o.z; pq[3] += o.w * o.w;
    }
#pragma unroll
    for (int cc = 0; cc < 4; cc++) {
        atomicAdd(&sS[tc * 4 + cc], ps[cc]);
        atomicAdd(&sQ[tc * 4 + cc], pq[cc]);
    }
    __syncthreads();
    if (tid < OUT_F) {
        atomicAdd(&g_s2[tid * SPAD], sS[tid]);
        atomicAdd(&g_q2[tid * SPAD], sQ[tid]);
    }
}

// ---------------- K5: decoder + BCE with fused BN2+ReLU ----------------
__global__ void k_loss(const int* __restrict__ target, const int* __restrict__ neg,
                       const float* __restrict__ g2, const float* __restrict__ be2,
                       const float* __restrict__ Wd, const float* __restrict__ bd,
                       float* __restrict__ out) {
    __shared__ float  sWd[OUT_F], sSc[OUT_F], sSh[OUT_F];
    __shared__ double sAcc[8];
    const int tid = threadIdx.x, w = tid >> 5, lane = tid & 31;
    const int grp = lane >> 3, hl = lane & 7;
    if (tid < OUT_F) {
        sWd[tid] = Wd[tid];
        const float mean = g_s2[tid * SPAD] * (1.f / (float)N_NODES);
        const float var  = g_q2[tid * SPAD] * (1.f / (float)N_NODES) - mean * mean;
        const float sc   = __ldg(&g2[tid]) * rsqrtf(fmaxf(var, 0.f) + EPS);
        sSc[tid] = sc;
        sSh[tid] = __ldg(&be2[tid]) - mean * sc;
    }
    __syncthreads();
    const float bdv = __ldg(&bd[0]);
    const float4 wd0  = *(const float4*)&sWd[hl * 8];
    const float4 wd1  = *(const float4*)&sWd[hl * 8 + 4];
    const float4 sca  = *(const float4*)&sSc[hl * 8];
    const float4 scb  = *(const float4*)&sSc[hl * 8 + 4];
    const float4 sha  = *(const float4*)&sSh[hl * 8];
    const float4 shb  = *(const float4*)&sSh[hl * 8 + 4];
    double acc = 0.0;
    const int p0 = blockIdx.x * 256;
    for (int it = 0; it < 8; it++) {
        const int p = p0 + it * 32 + w * 4 + grp;
        float d = 0.f; float label = 0.f; bool live = (p < 2 * NE);
        if (live) {
            int a, b;
            if (p < NE) { a = __ldg(&target[p]);   b = __ldg(&target[NE + p]); label = 1.f; }
            else        { a = __ldg(&neg[p - NE]); b = __ldg(&neg[p]);         label = 0.f; }
            const float4 va0 = *(const float4*)&g_pre2[(size_t)a * OUT_F + hl * 8];
            const float4 va1 = *(const float4*)&g_pre2[(size_t)a * OUT_F + hl * 8 + 4];
            const float4 vb0 = *(const float4*)&g_pre2[(size_t)b * OUT_F + hl * 8];
            const float4 vb1 = *(const float4*)&g_pre2[(size_t)b * OUT_F + hl * 8 + 4];
            float4 ea0, ea1, eb0, eb1;
            ea0.x = fmaxf(fmaf(va0.x, sca.x, sha.x), 0.f);
            ea0.y = fmaxf(fmaf(va0.y, sca.y, sha.y), 0.f);
            ea0.z = fmaxf(fmaf(va0.z, sca.z, sha.z), 0.f);
            ea0.w = fmaxf(fmaf(va0.w, sca.w, sha.w), 0.f);
            ea1.x = fmaxf(fmaf(va1.x, scb.x, shb.x), 0.f);
            ea1.y = fmaxf(fmaf(va1.y, scb.y, shb.y), 0.f);
            ea1.z = fmaxf(fmaf(va1.z, scb.z, shb.z), 0.f);
            ea1.w = fmaxf(fmaf(va1.w, scb.w, shb.w), 0.f);
            eb0.x = fmaxf(fmaf(vb0.x, sca.x, sha.x), 0.f);
            eb0.y = fmaxf(fmaf(vb0.y, sca.y, sha.y), 0.f);
            eb0.z = fmaxf(fmaf(vb0.z, sca.z, sha.z), 0.f);
            eb0.w = fmaxf(fmaf(vb0.w, sca.w, sha.w), 0.f);
            eb1.x = fmaxf(fmaf(vb1.x, scb.x, shb.x), 0.f);
            eb1.y = fmaxf(fmaf(vb1.y, scb.y, shb.y), 0.f);
            eb1.z = fmaxf(fmaf(vb1.z, scb.z, shb.z), 0.f);
            eb1.w = fmaxf(fmaf(vb1.w, scb.w, shb.w), 0.f);
            d = ea0.x * eb0.x * wd0.x + ea0.y * eb0.y * wd0.y
              + ea0.z * eb0.z * wd0.z + ea0.w * eb0.w * wd0.w
              + ea1.x * eb1.x * wd1.x + ea1.y * eb1.y * wd1.y
              + ea1.z * eb1.z * wd1.z + ea1.w * eb1.w * wd1.w;
        }
#pragma unroll
        for (int off = 4; off; off >>= 1) d += __shfl_xor_sync(0xffffffff, d, off);
        if (hl == 0 && live) {
            const float pl   = d + bdv;
            const float term = fmaxf(pl, 0.f) - pl * label + log1pf(__expf(-fabsf(pl)));
            acc += (double)term;
        }
    }
    acc += __shfl_xor_sync(0xffffffff, acc, 8);
    acc += __shfl_xor_sync(0xffffffff, acc, 16);
    if (lane == 0) sAcc[w] = acc;
    __syncthreads();
    if (tid == 0) {
        double s = 0.0;
#pragma unroll
        for (int k = 0; k < 8; k++) s += sAcc[k];
        atomicAdd(&g_loss, s);
        __threadfence();
        const int dn = atomicAdd(&g_done, 1);
        if (dn == (int)gridDim.x - 1)
            out[0] = (float)(g_loss * (1.0 / (2.0 * (double)NE)));
    }
}

// ---------------- launch ----------------
extern "C" void kernel_launch(void* const* d_in, const int* in_sizes, int n_in,
                              void* d_out, int out_size) {
    const float* x       = (const float*)d_in[0];
    const float* node_ts = (const float*)d_in[1];
    const int*   nbi     = (const int*)  d_in[2];
    const float* nbt     = (const float*)d_in[3];
    const int*   target  = (const int*)  d_in[4];
    const int*   neg     = (const int*)  d_in[5];
    const float* W1      = (const float*)d_in[6];
    const float* b1      = (const float*)d_in[7];
    const float* g1      = (const float*)d_in[8];
    const float* be1     = (const float*)d_in[9];
    const float* W2      = (const float*)d_in[10];
    const float* b2      = (const float*)d_in[11];
    const float* g2      = (const float*)d_in[12];
    const float* be2     = (const float*)d_in[13];
    const float* Wd      = (const float*)d_in[14];
    const float* bd      = (const float*)d_in[15];
    float* out = (float*)d_out;

    k_zero   <<<(N_NODES + 255) / 256, 256>>>(nbi, nbt);
    k_gemm1  <<<N_NODES / 32, 128>>>(x, W1);
    k_widx   <<<(M_ROWS + 255) / 256, 256>>>(node_ts, nbi, nbt);
    k_pref   <<<N_NODES / 8, 256>>>(b1);                          // <- profiled (4th)
    k_bngemm2<<<N_NODES / 32, 256>>>(g1, be1, b1, W2, b2);
    k_loss   <<<(2 * NE + 255) / 256, 256>>>(target, neg, g2, be2, Wd, bd, out);
}

// round 15
// speedup vs baseline: 1.2133x; 1.1455x over previous
#include <cuda_runtime.h>
#include <cuda_fp16.h>
#include <math.h>

#define N_NODES 20000
#define D 8
#define DP1 9
#define M_ROWS (N_NODES * DP1)   // 180000
#define IN_F 64
#define HID 128
#define OUT_F 64
#define NE 100000
#define EPS 1e-5f
#define SPAD 64

// ---------------- scratch ----------------
__device__ __half g_y1h[N_NODES * HID];       // x @ W1, fp16 (5.12 MB)
__device__ __half g_prefh[M_ROWS * HID];      // fp16 prefix rows (46 MB)
__device__ float  g_pre2[N_NODES * OUT_F];
__device__ float  g_sts[N_NODES * D];         // per-node ts-sorted neighbor ts
__device__ int    g_sgi[N_NODES * D];         // per-node ts-sorted neighbor idx
__device__ int    g_w[M_ROWS];                // multiplicity of (child, idx)
__device__ int    g_qkey[M_ROWS];             // (row<<4)|idx, ~x if mask2-invalid
__device__ float  g_s1[HID * SPAD],  g_q1[HID * SPAD];
__device__ float  g_s2[OUT_F * SPAD], g_q2[OUT_F * SPAD];
__device__ double g_loss;
__device__ int    g_done;

// ---------------- K0: zero accumulators + sort each node's neighbors by ts ----------------
__global__ void k_zero(const int* __restrict__ nbi, const float* __restrict__ nbt) {
    const int t = blockIdx.x * blockDim.x + threadIdx.x;
    if (blockIdx.x == 0) {
        const int tid = threadIdx.x;
        if (tid < HID)   { g_s1[tid * SPAD] = 0.f; g_q1[tid * SPAD] = 0.f; }
        if (tid < OUT_F) { g_s2[tid * SPAD] = 0.f; g_q2[tid * SPAD] = 0.f; }
        if (tid == 0)    { g_loss = 0.0; g_done = 0; }
    }
    if (t >= N_NODES) return;
#pragma unroll
    for (int k = 0; k < DP1; k++) g_w[t * DP1 + k] = 0;
    float ts[D]; int gi[D];
    const float4 t0 = __ldg((const float4*)&nbt[t * D]);
    const float4 t1 = __ldg((const float4*)&nbt[t * D + 4]);
    const int4   i0 = __ldg((const int4*)&nbi[t * D]);
    const int4   i1 = __ldg((const int4*)&nbi[t * D + 4]);
    ts[0]=t0.x; ts[1]=t0.y; ts[2]=t0.z; ts[3]=t0.w;
    ts[4]=t1.x; ts[5]=t1.y; ts[6]=t1.z; ts[7]=t1.w;
    gi[0]=i0.x; gi[1]=i0.y; gi[2]=i0.z; gi[3]=i0.w;
    gi[4]=i1.x; gi[5]=i1.y; gi[6]=i1.z; gi[7]=i1.w;
#define CE(a, b) { bool p = ts[a] > ts[b]; \
    float tA = ts[a], tB = ts[b]; ts[a] = p ? tB : tA; ts[b] = p ? tA : tB; \
    int   iA = gi[a], iB = gi[b]; gi[a] = p ? iB : iA; gi[b] = p ? iA : iB; }
    CE(0,1) CE(2,3) CE(4,5) CE(6,7)
    CE(0,2) CE(1,3) CE(4,6) CE(5,7)
    CE(1,2) CE(5,6)
    CE(0,4) CE(1,5) CE(2,6) CE(3,7)
    CE(2,4) CE(3,5)
    CE(1,2) CE(3,4) CE(5,6)
#undef CE
    *(float4*)&g_sts[t * D]     = make_float4(ts[0], ts[1], ts[2], ts[3]);
    *(float4*)&g_sts[t * D + 4] = make_float4(ts[4], ts[5], ts[6], ts[7]);
    *(int4*)&g_sgi[t * D]       = make_int4(gi[0], gi[1], gi[2], gi[3]);
    *(int4*)&g_sgi[t * D + 4]   = make_int4(gi[4], gi[5], gi[6], gi[7]);
}

// ---------------- K1: y1 = x @ W1 (fp16 output) ----------------
__global__ void k_gemm1(const float* __restrict__ x, const float* __restrict__ W1) {
    __shared__ float sX[32 * IN_F];
    __shared__ float sW[IN_F * HID];
    const int tid  = threadIdx.x;
    const int row0 = blockIdx.x * 32;
    for (int i = tid; i < 32 * IN_F; i += 128) sX[i] = x[(size_t)row0 * IN_F + i];
    for (int i = tid; i < IN_F * HID; i += 128) sW[i] = W1[i];
    __syncthreads();
    const int tr = tid >> 5;
    const int tc = tid & 31;
    float acc[8][4];
#pragma unroll
    for (int r = 0; r < 8; r++)
#pragma unroll
        for (int c = 0; c < 4; c++) acc[r][c] = 0.f;
#pragma unroll 8
    for (int f = 0; f < IN_F; f++) {
        const float4 w = *(const float4*)&sW[f * HID + tc * 4];
#pragma unroll
        for (int r = 0; r < 8; r++) {
            const float a = sX[(tr * 8 + r) * IN_F + f];
            acc[r][0] = fmaf(a, w.x, acc[r][0]);
            acc[r][1] = fmaf(a, w.y, acc[r][1]);
            acc[r][2] = fmaf(a, w.z, acc[r][2]);
            acc[r][3] = fmaf(a, w.w, acc[r][3]);
        }
    }
#pragma unroll
    for (int r = 0; r < 8; r++) {
        union { __half2 h[2]; uint2 u; } pk;
        pk.h[0] = __floats2half2_rn(acc[r][0], acc[r][1]);
        pk.h[1] = __floats2half2_rn(acc[r][2], acc[r][3]);
        *(uint2*)&g_y1h[(size_t)(row0 + tr * 8 + r) * HID + tc * 4] = pk.u;
    }
}

// ---------------- K2: per-query (child, idx) key + multiplicity histogram ----------------
__global__ void k_widx(const float* __restrict__ node_ts,
                       const int*   __restrict__ nbi,
                       const float* __restrict__ nbt) {
    const int q = blockIdx.x * blockDim.x + threadIdx.x;
    if (q >= M_ROWS) return;
    const int i = q / DP1;
    const int j = q - i * DP1;
    const float ts_i = __ldg(&node_ts[i]);
    int ci; float cts;
    if (j < D) { ci = __ldg(&nbi[i * D + j]); cts = __ldg(&nbt[i * D + j]); }
    else       { ci = i;                      cts = ts_i; }
    const bool valid = (cts <= ts_i);
    const float4 t0 = __ldg((const float4*)&g_sts[ci * D]);
    const float4 t1 = __ldg((const float4*)&g_sts[ci * D + 4]);
    int idx = (t0.x <= cts) + (t0.y <= cts) + (t0.z <= cts) + (t0.w <= cts)
            + (t1.x <= cts) + (t1.y <= cts) + (t1.z <= cts) + (t1.w <= cts);
    const int rowid = ci * DP1 + idx;
    atomicAdd(&g_w[rowid], 1);
    const int key = (rowid << 4) | idx;
    g_qkey[q] = valid ? key : ~key;
}

// ---------------- K3: per-node prefix rows + weighted BN1 stats -- PROFILED SLOT ----------------
// 8 warps/block, warp per node; stats via per-warp STS + tree reduce (no shared atomics).
__global__ void k_pref(const float* __restrict__ b1) {
    __shared__ float sSp[8 * HID];   // 4 KB: per-warp ps partials
    __shared__ float sQp[8 * HID];   // 4 KB: per-warp pq partials
    const int tid  = threadIdx.x;
    const int w8   = tid >> 5, lane = tid & 31;
    const int c = blockIdx.x * 8 + w8;

    int gi[D];
    {
        const int4 i0 = __ldg((const int4*)&g_sgi[c * D]);
        const int4 i1 = __ldg((const int4*)&g_sgi[c * D + 4]);
        gi[0]=i0.x; gi[1]=i0.y; gi[2]=i0.z; gi[3]=i0.w;
        gi[4]=i1.x; gi[5]=i1.y; gi[6]=i1.z; gi[7]=i1.w;
    }
    int wq[DP1];
#pragma unroll
    for (int k = 0; k < DP1; k++) wq[k] = __ldg(&g_w[c * DP1 + k]);

    union U2 { __half2 h[2]; uint2 u; };
    U2 row[D];
#pragma unroll
    for (int k = 0; k < D; k++)
        row[k].u = *(const uint2*)&g_y1h[(size_t)gi[k] * HID + lane * 4];
    U2 p; p.u = *(const uint2*)&g_y1h[(size_t)c * HID + lane * 4];

    const float4 bb = *(const float4*)&b1[lane * 4];
    float4 ps = make_float4(0.f, 0.f, 0.f, 0.f);
    float4 pq = make_float4(0.f, 0.f, 0.f, 0.f);
#pragma unroll
    for (int k = 0; k < DP1; k++) {
        if (k > 0) {
            p.h[0] = __hadd2(p.h[0], row[k - 1].h[0]);
            p.h[1] = __hadd2(p.h[1], row[k - 1].h[1]);
        }
        if (wq[k] > 0)   // warp-uniform
            *(uint2*)&g_prefh[(size_t)(c * DP1 + k) * HID + lane * 4] = p.u;
        const float wf  = (float)wq[k];
        const float inv = 1.f / (float)(k + 1);    // compile-time constant
        const float2 f0 = __half22float2(p.h[0]);
        const float2 f1 = __half22float2(p.h[1]);
        float4 v;
        v.x = fmaf(f0.x, inv, bb.x);
        v.y = fmaf(f0.y, inv, bb.y);
        v.z = fmaf(f1.x, inv, bb.z);
        v.w = fmaf(f1.y, inv, bb.w);
        ps.x += wf * v.x; ps.y += wf * v.y; ps.z += wf * v.z; ps.w += wf * v.w;
        pq.x += wf * v.x * v.x; pq.y += wf * v.y * v.y;
        pq.z += wf * v.z * v.z; pq.w += wf * v.w * v.w;
    }
    // per-warp partial store (conflict-free), then tree reduce
    *(float4*)&sSp[w8 * HID + lane * 4] = ps;
    *(float4*)&sQp[w8 * HID + lane * 4] = pq;
    __syncthreads();
    if (tid < HID) {
        float s = 0.f, q = 0.f;
#pragma unroll
        for (int k = 0; k < 8; k++) {
            s += sSp[k * HID + tid];
            q += sQp[k * HID + tid];
        }
        atomicAdd(&g_s1[tid * SPAD], s);
        atomicAdd(&g_q1[tid * SPAD], q);
    }
}

// ---------------- K4: fused BN1+ReLU masked-mean -> gemm2 + BN2 partials ----------------
// 256 thr; 32 nodes/block; rows gathered via qkey; stats via sA-reuse tree reduce.
__global__ void k_bngemm2(const float* __restrict__ g1, const float* __restrict__ be1,
                          const float* __restrict__ b1,
                          const float* __restrict__ W2, const float* __restrict__ b2) {
    __shared__ float sA[32 * HID];      // 16 KB (agg2 tile; reused for stat partials)
    __shared__ float sW[HID * OUT_F];   // 32 KB
    __shared__ float sSc[HID], sShp[HID];
    const int tid  = threadIdx.x;
    const int w    = tid >> 5, lane = tid & 31;
    const int row0 = blockIdx.x * 32;
    for (int i = tid; i < HID * OUT_F; i += 256) sW[i] = W2[i];
    if (tid < HID) {
        const float mean = g_s1[tid * SPAD] * (1.f / (float)M_ROWS);
        const float var  = g_q1[tid * SPAD] * (1.f / (float)M_ROWS) - mean * mean;
        const float sc   = __ldg(&g1[tid]) * rsqrtf(fmaxf(var, 0.f) + EPS);
        sSc[tid]  = sc;
        sShp[tid] = fmaf(__ldg(&b1[tid]) - mean, sc, __ldg(&be1[tid]));
    }
    __syncthreads();
    const float4 sc4 = *(const float4*)&sSc[lane * 4];
    const float4 sp4 = *(const float4*)&sShp[lane * 4];
#pragma unroll
    for (int half = 0; half < 2; half++) {
        const int iA = row0 + w * 4 + half * 2;
        const int iB = iA + 1;
        int keyA[DP1], keyB[DP1];
#pragma unroll
        for (int j = 0; j < DP1; j++) {
            keyA[j] = __ldg(&g_qkey[iA * DP1 + j]);
            keyB[j] = __ldg(&g_qkey[iB * DP1 + j]);
        }
        bool vA[DP1], vB[DP1];
        int rwA[DP1], rwB[DP1];
        float ivA[DP1], ivB[DP1];
        float cntA = 0.f, cntB = 0.f;
#pragma unroll
        for (int j = 0; j < DP1; j++) {
            vA[j] = keyA[j] >= 0;  int kA = vA[j] ? keyA[j] : ~keyA[j];
            vB[j] = keyB[j] >= 0;  int kB = vB[j] ? keyB[j] : ~keyB[j];
            rwA[j] = kA >> 4;      ivA[j] = __fdividef(1.f, (float)((kA & 15) + 1));
            rwB[j] = kB >> 4;      ivB[j] = __fdividef(1.f, (float)((kB & 15) + 1));
            cntA += vA[j] ? 1.f : 0.f;
            cntB += vB[j] ? 1.f : 0.f;
        }
        uint2 rA[DP1], rB[DP1];
#pragma unroll
        for (int j = 0; j < DP1; j++) {
            rA[j] = *(const uint2*)&g_prefh[(size_t)rwA[j] * HID + lane * 4];
            rB[j] = *(const uint2*)&g_prefh[(size_t)rwB[j] * HID + lane * 4];
        }
        {
            float4 acc = make_float4(0.f, 0.f, 0.f, 0.f);
#pragma unroll
            for (int j = 0; j < DP1; j++) {
                const float2 a0 = __half22float2(*(__half2*)&rA[j].x);
                const float2 a1 = __half22float2(*(__half2*)&rA[j].y);
                const float iv = ivA[j];
                acc.x += vA[j] ? fmaxf(fmaf(a0.x * iv, sc4.x, sp4.x), 0.f) : 0.f;
                acc.y += vA[j] ? fmaxf(fmaf(a0.y * iv, sc4.y, sp4.y), 0.f) : 0.f;
                acc.z += vA[j] ? fmaxf(fmaf(a1.x * iv, sc4.z, sp4.z), 0.f) : 0.f;
                acc.w += vA[j] ? fmaxf(fmaf(a1.y * iv, sc4.w, sp4.w), 0.f) : 0.f;
            }
            const float inv = __fdividef(1.f, cntA);
            *(float4*)&sA[(w * 4 + half * 2) * HID + lane * 4] =
                make_float4(acc.x * inv, acc.y * inv, acc.z * inv, acc.w * inv);
        }
        {
            float4 acc = make_float4(0.f, 0.f, 0.f, 0.f);
#pragma unroll
            for (int j = 0; j < DP1; j++) {
                const float2 a0 = __half22float2(*(__half2*)&rB[j].x);
                const float2 a1 = __half22float2(*(__half2*)&rB[j].y);
                const float iv = ivB[j];
                acc.x += vB[j] ? fmaxf(fmaf(a0.x * iv, sc4.x, sp4.x), 0.f) : 0.f;
                acc.y += vB[j] ? fmaxf(fmaf(a0.y * iv, sc4.y, sp4.y), 0.f) : 0.f;
                acc.z += vB[j] ? fmaxf(fmaf(a1.x * iv, sc4.z, sp4.z), 0.f) : 0.f;
                acc.w += vB[j] ? fmaxf(fmaf(a1.y * iv, sc4.w, sp4.w), 0.f) : 0.f;
            }
            const float inv = __fdividef(1.f, cntB);
            *(float4*)&sA[(w * 4 + half * 2 + 1) * HID + lane * 4] =
                make_float4(acc.x * inv, acc.y * inv, acc.z * inv, acc.w * inv);
        }
    }
    __syncthreads();
    const int tr = tid >> 4;
    const int tc = tid & 15;
    float acc[2][4];
#pragma unroll
    for (int r = 0; r < 2; r++)
#pragma unroll
        for (int cc = 0; cc < 4; cc++) acc[r][cc] = 0.f;
#pragma unroll 8
    for (int f = 0; f < HID; f++) {
        const float4 wv = *(const float4*)&sW[f * OUT_F + tc * 4];
#pragma unroll
        for (int r = 0; r < 2; r++) {
            const float a = sA[(tr * 2 + r) * HID + f];
            acc[r][0] = fmaf(a, wv.x, acc[r][0]);
            acc[r][1] = fmaf(a, wv.y, acc[r][1]);
            acc[r][2] = fmaf(a, wv.z, acc[r][2]);
            acc[r][3] = fmaf(a, wv.w, acc[r][3]);
        }
    }
    const float4 bbv = *(const float4*)&b2[tc * 4];
    float ps[4] = {0.f, 0.f, 0.f, 0.f}, pq[4] = {0.f, 0.f, 0.f, 0.f};
#pragma unroll
    for (int r = 0; r < 2; r++) {
        float4 o = make_float4(acc[r][0] + bbv.x, acc[r][1] + bbv.y,
                               acc[r][2] + bbv.z, acc[r][3] + bbv.w);
        *(float4*)&g_pre2[(size_t)(row0 + tr * 2 + r) * OUT_F + tc * 4] = o;
        ps[0] += o.x; ps[1] += o.y; ps[2] += o.z; ps[3] += o.w;
        pq[0] += o.x * o.x; pq[1] += o.y * o.y; pq[2] += o.z * o.z; pq[3] += o.w * o.w;
    }
    // stats: reuse sA as [16][OUT_F] ps-partials + [16][OUT_F] pq-partials
    __syncthreads();                       // everyone done reading sA
    *(float4*)&sA[tr * OUT_F + tc * 4]                 = make_float4(ps[0], ps[1], ps[2], ps[3]);
    *(float4*)&sA[16 * OUT_F + tr * OUT_F + tc * 4]    = make_float4(pq[0], pq[1], pq[2], pq[3]);
    __syncthreads();
    if (tid < OUT_F) {
        float s = 0.f, q = 0.f;
#pragma unroll
        for (int k = 0; k < 16; k++) {
            s += sA[k * OUT_F + tid];
            q += sA[16 * OUT_F + k * OUT_F + tid];
        }
        atomicAdd(&g_s2[tid * SPAD], s);
        atomicAdd(&g_q2[tid * SPAD], q);
    }
}

// ---------------- K5: decoder + BCE with fused BN2+ReLU ----------------
__global__ void k_loss(const int* __restrict__ target, const int* __restrict__ neg,
                       const float* __restrict__ g2, const float* __restrict__ be2,
                       const float* __restrict__ Wd, const float* __restrict__ bd,
                       float* __restrict__ out) {
    __shared__ float  sWd[OUT_F], sSc[OUT_F], sSh[OUT_F];
    __shared__ double sAcc[8];
    const int tid = threadIdx.x, w = tid >> 5, lane = tid & 31;
    const int grp = lane >> 3, hl = lane & 7;
    if (tid < OUT_F) {
        sWd[tid] = Wd[tid];
        const float mean = g_s2[tid * SPAD] * (1.f / (float)N_NODES);
        const float var  = g_q2[tid * SPAD] * (1.f / (float)N_NODES) - mean * mean;
        const float sc   = __ldg(&g2[tid]) * rsqrtf(fmaxf(var, 0.f) + EPS);
        sSc[tid] = sc;
        sSh[tid] = __ldg(&be2[tid]) - mean * sc;
    }
    __syncthreads();
    const float bdv = __ldg(&bd[0]);
    const float4 wd0  = *(const float4*)&sWd[hl * 8];
    const float4 wd1  = *(const float4*)&sWd[hl * 8 + 4];
    const float4 sca  = *(const float4*)&sSc[hl * 8];
    const float4 scb  = *(const float4*)&sSc[hl * 8 + 4];
    const float4 sha  = *(const float4*)&sSh[hl * 8];
    const float4 shb  = *(const float4*)&sSh[hl * 8 + 4];
    double acc = 0.0;
    const int p0 = blockIdx.x * 256;
    for (int it = 0; it < 8; it++) {
        const int p = p0 + it * 32 + w * 4 + grp;
        float d = 0.f; float label = 0.f; bool live = (p < 2 * NE);
        if (live) {
            int a, b;
            if (p < NE) { a = __ldg(&target[p]);   b = __ldg(&target[NE + p]); label = 1.f; }
            else        { a = __ldg(&neg[p - NE]); b = __ldg(&neg[p]);         label = 0.f; }
            const float4 va0 = *(const float4*)&g_pre2[(size_t)a * OUT_F + hl * 8];
            const float4 va1 = *(const float4*)&g_pre2[(size_t)a * OUT_F + hl * 8 + 4];
            const float4 vb0 = *(const float4*)&g_pre2[(size_t)b * OUT_F + hl * 8];
            const float4 vb1 = *(const float4*)&g_pre2[(size_t)b * OUT_F + hl * 8 + 4];
            float4 ea0, ea1, eb0, eb1;
            ea0.x = fmaxf(fmaf(va0.x, sca.x, sha.x), 0.f);
            ea0.y = fmaxf(fmaf(va0.y, sca.y, sha.y), 0.f);
            ea0.z = fmaxf(fmaf(va0.z, sca.z, sha.z), 0.f);
            ea0.w = fmaxf(fmaf(va0.w, sca.w, sha.w), 0.f);
            ea1.x = fmaxf(fmaf(va1.x, scb.x, shb.x), 0.f);
            ea1.y = fmaxf(fmaf(va1.y, scb.y, shb.y), 0.f);
            ea1.z = fmaxf(fmaf(va1.z, scb.z, shb.z), 0.f);
            ea1.w = fmaxf(fmaf(va1.w, scb.w, shb.w), 0.f);
            eb0.x = fmaxf(fmaf(vb0.x, sca.x, sha.x), 0.f);
            eb0.y = fmaxf(fmaf(vb0.y, sca.y, sha.y), 0.f);
            eb0.z = fmaxf(fmaf(vb0.z, sca.z, sha.z), 0.f);
            eb0.w = fmaxf(fmaf(vb0.w, sca.w, sha.w), 0.f);
            eb1.x = fmaxf(fmaf(vb1.x, scb.x, shb.x), 0.f);
            eb1.y = fmaxf(fmaf(vb1.y, scb.y, shb.y), 0.f);
            eb1.z = fmaxf(fmaf(vb1.z, scb.z, shb.z), 0.f);
            eb1.w = fmaxf(fmaf(vb1.w, scb.w, shb.w), 0.f);
            d = ea0.x * eb0.x * wd0.x + ea0.y * eb0.y * wd0.y
              + ea0.z * eb0.z * wd0.z + ea0.w * eb0.w * wd0.w
              + ea1.x * eb1.x * wd1.x + ea1.y * eb1.y * wd1.y
              + ea1.z * eb1.z * wd1.z + ea1.w * eb1.w * wd1.w;
        }
#pragma unroll
        for (int off = 4; off; off >>= 1) d += __shfl_xor_sync(0xffffffff, d, off);
        if (hl == 0 && live) {
            const float pl   = d + bdv;
            const float term = fmaxf(pl, 0.f) - pl * label + log1pf(__expf(-fabsf(pl)));
            acc += (double)term;
        }
    }
    acc += __shfl_xor_sync(0xffffffff, acc, 8);
    acc += __shfl_xor_sync(0xffffffff, acc, 16);
    if (lane == 0) sAcc[w] = acc;
    __syncthreads();
    if (tid == 0) {
        double s = 0.0;
#pragma unroll
        for (int k = 0; k < 8; k++) s += sAcc[k];
        atomicAdd(&g_loss, s);
        __threadfence();
        const int dn = atomicAdd(&g_done, 1);
        if (dn == (int)gridDim.x - 1)
            out[0] = (float)(g_loss * (1.0 / (2.0 * (double)NE)));
    }
}

// ---------------- launch ----------------
extern "C" void kernel_launch(void* const* d_in, const int* in_sizes, int n_in,
                              void* d_out, int out_size) {
    const float* x       = (const float*)d_in[0];
    const float* node_ts = (const float*)d_in[1];
    const int*   nbi     = (const int*)  d_in[2];
    const float* nbt     = (const float*)d_in[3];
    const int*   target  = (const int*)  d_in[4];
    const int*   neg     = (const int*)  d_in[5];
    const float* W1      = (const float*)d_in[6];
    const float* b1      = (const float*)d_in[7];
    const float* g1      = (const float*)d_in[8];
    const float* be1     = (const float*)d_in[9];
    const float* W2      = (const float*)d_in[10];
    const float* b2      = (const float*)d_in[11];
    const float* g2      = (const float*)d_in[12];
    const float* be2     = (const float*)d_in[13];
    const float* Wd      = (const float*)d_in[14];
    const float* bd      = (const float*)d_in[15];
    float* out = (float*)d_out;

    k_zero   <<<(N_NODES + 255) / 256, 256>>>(nbi, nbt);
    k_gemm1  <<<N_NODES / 32, 128>>>(x, W1);
    k_widx   <<<(M_ROWS + 255) / 256, 256>>>(node_ts, nbi, nbt);
    k_pref   <<<N_NODES / 8, 256>>>(b1);                          // <- profiled (4th)
    k_bngemm2<<<N_NODES / 32, 256>>>(g1, be1, b1, W2, b2);
    k_loss   <<<(2 * NE + 255) / 256, 256>>>(target, neg, g2, be2, Wd, bd, out);
}

// round 16
// speedup vs baseline: 1.3139x; 1.0829x over previous
#include <cuda_runtime.h>
#include <cuda_fp16.h>
#include <math.h>

#define N_NODES 20000
#define D 8
#define DP1 9
#define M_ROWS (N_NODES * DP1)   // 180000
#define IN_F 64
#define HID 128
#define OUT_F 64
#define NE 100000
#define EPS 1e-5f
#define SPAD 64

// ---------------- scratch ----------------
__device__ __half g_y1h[N_NODES * HID];       // x @ W1, fp16 (5.12 MB)
__device__ __half g_prefh[M_ROWS * HID];      // fp16 prefix rows (46 MB)
__device__ __half g_pre2h[N_NODES * OUT_F];   // fp16 pre2 (2.56 MB)
__device__ float  g_sts[N_NODES * D];         // per-node ts-sorted neighbor ts
__device__ int    g_sgi[N_NODES * D];         // per-node ts-sorted neighbor idx
__device__ int    g_w[M_ROWS];                // multiplicity of (child, idx)
__device__ int    g_qkey[M_ROWS];             // (row<<4)|idx, ~x if mask2-invalid
__device__ float  g_s1[HID * SPAD],  g_q1[HID * SPAD];
__device__ float  g_s2[OUT_F * SPAD], g_q2[OUT_F * SPAD];
__device__ double g_loss;
__device__ int    g_done;

// ---------------- K1: y1 = x @ W1 (fp16 out) + fused zero/sort prologue ----------------
__global__ void k_gemm1(const float* __restrict__ x, const float* __restrict__ W1,
                        const int* __restrict__ nbi, const float* __restrict__ nbt) {
    __shared__ float sX[32 * IN_F];
    __shared__ float sW[IN_F * HID];
    const int tid  = threadIdx.x;
    const int row0 = blockIdx.x * 32;
    // ---- fused per-replay zero + neighbor sort (first 157 blocks) ----
    const int t = blockIdx.x * 128 + tid;
    if (blockIdx.x == 0) {
        if (tid < HID)   { g_s1[tid * SPAD] = 0.f; g_q1[tid * SPAD] = 0.f; }
        if (tid < OUT_F) { g_s2[tid * SPAD] = 0.f; g_q2[tid * SPAD] = 0.f; }
        if (tid == 0)    { g_loss = 0.0; g_done = 0; }
    }
    if (t < N_NODES) {
#pragma unroll
        for (int k = 0; k < DP1; k++) g_w[t * DP1 + k] = 0;
        float ts[D]; int gi[D];
        const float4 t0 = __ldg((const float4*)&nbt[t * D]);
        const float4 t1 = __ldg((const float4*)&nbt[t * D + 4]);
        const int4   i0 = __ldg((const int4*)&nbi[t * D]);
        const int4   i1 = __ldg((const int4*)&nbi[t * D + 4]);
        ts[0]=t0.x; ts[1]=t0.y; ts[2]=t0.z; ts[3]=t0.w;
        ts[4]=t1.x; ts[5]=t1.y; ts[6]=t1.z; ts[7]=t1.w;
        gi[0]=i0.x; gi[1]=i0.y; gi[2]=i0.z; gi[3]=i0.w;
        gi[4]=i1.x; gi[5]=i1.y; gi[6]=i1.z; gi[7]=i1.w;
#define CE(a, b) { bool p = ts[a] > ts[b]; \
    float tA = ts[a], tB = ts[b]; ts[a] = p ? tB : tA; ts[b] = p ? tA : tB; \
    int   iA = gi[a], iB = gi[b]; gi[a] = p ? iB : iA; gi[b] = p ? iA : iB; }
        CE(0,1) CE(2,3) CE(4,5) CE(6,7)
        CE(0,2) CE(1,3) CE(4,6) CE(5,7)
        CE(1,2) CE(5,6)
        CE(0,4) CE(1,5) CE(2,6) CE(3,7)
        CE(2,4) CE(3,5)
        CE(1,2) CE(3,4) CE(5,6)
#undef CE
        *(float4*)&g_sts[t * D]     = make_float4(ts[0], ts[1], ts[2], ts[3]);
        *(float4*)&g_sts[t * D + 4] = make_float4(ts[4], ts[5], ts[6], ts[7]);
        *(int4*)&g_sgi[t * D]       = make_int4(gi[0], gi[1], gi[2], gi[3]);
        *(int4*)&g_sgi[t * D + 4]   = make_int4(gi[4], gi[5], gi[6], gi[7]);
    }
    // ---- GEMM ----
    for (int i = tid; i < 32 * IN_F; i += 128) sX[i] = x[(size_t)row0 * IN_F + i];
    for (int i = tid; i < IN_F * HID; i += 128) sW[i] = W1[i];
    __syncthreads();
    const int tr = tid >> 5;
    const int tc = tid & 31;
    float acc[8][4];
#pragma unroll
    for (int r = 0; r < 8; r++)
#pragma unroll
        for (int c = 0; c < 4; c++) acc[r][c] = 0.f;
#pragma unroll 8
    for (int f = 0; f < IN_F; f++) {
        const float4 w = *(const float4*)&sW[f * HID + tc * 4];
#pragma unroll
        for (int r = 0; r < 8; r++) {
            const float a = sX[(tr * 8 + r) * IN_F + f];
            acc[r][0] = fmaf(a, w.x, acc[r][0]);
            acc[r][1] = fmaf(a, w.y, acc[r][1]);
            acc[r][2] = fmaf(a, w.z, acc[r][2]);
            acc[r][3] = fmaf(a, w.w, acc[r][3]);
        }
    }
#pragma unroll
    for (int r = 0; r < 8; r++) {
        union { __half2 h[2]; uint2 u; } pk;
        pk.h[0] = __floats2half2_rn(acc[r][0], acc[r][1]);
        pk.h[1] = __floats2half2_rn(acc[r][2], acc[r][3]);
        *(uint2*)&g_y1h[(size_t)(row0 + tr * 8 + r) * HID + tc * 4] = pk.u;
    }
}

// ---------------- K2: per-query (child, idx) key + multiplicity histogram ----------------
__global__ void k_widx(const float* __restrict__ node_ts,
                       const int*   __restrict__ nbi,
                       const float* __restrict__ nbt) {
    const int q = blockIdx.x * blockDim.x + threadIdx.x;
    if (q >= M_ROWS) return;
    const int i = q / DP1;
    const int j = q - i * DP1;
    const float ts_i = __ldg(&node_ts[i]);
    int ci; float cts;
    if (j < D) { ci = __ldg(&nbi[i * D + j]); cts = __ldg(&nbt[i * D + j]); }
    else       { ci = i;                      cts = ts_i; }
    const bool valid = (cts <= ts_i);
    const float4 t0 = __ldg((const float4*)&g_sts[ci * D]);
    const float4 t1 = __ldg((const float4*)&g_sts[ci * D + 4]);
    int idx = (t0.x <= cts) + (t0.y <= cts) + (t0.z <= cts) + (t0.w <= cts)
            + (t1.x <= cts) + (t1.y <= cts) + (t1.z <= cts) + (t1.w <= cts);
    const int rowid = ci * DP1 + idx;
    atomicAdd(&g_w[rowid], 1);
    const int key = (rowid << 4) | idx;
    g_qkey[q] = valid ? key : ~key;
}

// ---------------- K3: per-node prefix rows + weighted BN1 stats ----------------
__global__ void k_pref(const float* __restrict__ b1) {
    __shared__ float sSp[8 * HID];
    __shared__ float sQp[8 * HID];
    const int tid  = threadIdx.x;
    const int w8   = tid >> 5, lane = tid & 31;
    const int c = blockIdx.x * 8 + w8;

    int gi[D];
    {
        const int4 i0 = __ldg((const int4*)&g_sgi[c * D]);
        const int4 i1 = __ldg((const int4*)&g_sgi[c * D + 4]);
        gi[0]=i0.x; gi[1]=i0.y; gi[2]=i0.z; gi[3]=i0.w;
        gi[4]=i1.x; gi[5]=i1.y; gi[6]=i1.z; gi[7]=i1.w;
    }
    int wq[DP1];
#pragma unroll
    for (int k = 0; k < DP1; k++) wq[k] = __ldg(&g_w[c * DP1 + k]);

    union U2 { __half2 h[2]; uint2 u; };
    U2 row[D];
#pragma unroll
    for (int k = 0; k < D; k++)
        row[k].u = *(const uint2*)&g_y1h[(size_t)gi[k] * HID + lane * 4];
    U2 p; p.u = *(const uint2*)&g_y1h[(size_t)c * HID + lane * 4];

    const float4 bb = *(const float4*)&b1[lane * 4];
    float4 ps = make_float4(0.f, 0.f, 0.f, 0.f);
    float4 pq = make_float4(0.f, 0.f, 0.f, 0.f);
#pragma unroll
    for (int k = 0; k < DP1; k++) {
        if (k > 0) {
            p.h[0] = __hadd2(p.h[0], row[k - 1].h[0]);
            p.h[1] = __hadd2(p.h[1], row[k - 1].h[1]);
        }
        if (wq[k] > 0)   // warp-uniform
            *(uint2*)&g_prefh[(size_t)(c * DP1 + k) * HID + lane * 4] = p.u;
        const float wf  = (float)wq[k];
        const float inv = 1.f / (float)(k + 1);
        const float2 f0 = __half22float2(p.h[0]);
        const float2 f1 = __half22float2(p.h[1]);
        float4 v;
        v.x = fmaf(f0.x, inv, bb.x);
        v.y = fmaf(f0.y, inv, bb.y);
        v.z = fmaf(f1.x, inv, bb.z);
        v.w = fmaf(f1.y, inv, bb.w);
        ps.x += wf * v.x; ps.y += wf * v.y; ps.z += wf * v.z; ps.w += wf * v.w;
        pq.x += wf * v.x * v.x; pq.y += wf * v.y * v.y;
        pq.z += wf * v.z * v.z; pq.w += wf * v.w * v.w;
    }
    *(float4*)&sSp[w8 * HID + lane * 4] = ps;
    *(float4*)&sQp[w8 * HID + lane * 4] = pq;
    __syncthreads();
    if (tid < HID) {
        float s = 0.f, q = 0.f;
#pragma unroll
        for (int k = 0; k < 8; k++) {
            s += sSp[k * HID + tid];
            q += sQp[k * HID + tid];
        }
        atomicAdd(&g_s1[tid * SPAD], s);
        atomicAdd(&g_q1[tid * SPAD], q);
    }
}

// ---------------- K4: fused BN1+ReLU masked-mean -> gemm2 + BN2 partials -- PROFILED ----------------
__global__ void k_bngemm2(const float* __restrict__ g1, const float* __restrict__ be1,
                          const float* __restrict__ b1,
                          const float* __restrict__ W2, const float* __restrict__ b2) {
    __shared__ float sA[32 * HID];      // 16 KB (agg2 tile; reused for stat partials)
    __shared__ float sW[HID * OUT_F];   // 32 KB
    __shared__ float sSc[HID], sShp[HID];
    const int tid  = threadIdx.x;
    const int w    = tid >> 5, lane = tid & 31;
    const int row0 = blockIdx.x * 32;
    for (int i = tid; i < HID * OUT_F; i += 256) sW[i] = W2[i];
    if (tid < HID) {
        const float mean = g_s1[tid * SPAD] * (1.f / (float)M_ROWS);
        const float var  = g_q1[tid * SPAD] * (1.f / (float)M_ROWS) - mean * mean;
        const float sc   = __ldg(&g1[tid]) * rsqrtf(fmaxf(var, 0.f) + EPS);
        sSc[tid]  = sc;
        sShp[tid] = fmaf(__ldg(&b1[tid]) - mean, sc, __ldg(&be1[tid]));
    }
    __syncthreads();
    const float4 sc4 = *(const float4*)&sSc[lane * 4];
    const float4 sp4 = *(const float4*)&sShp[lane * 4];
#pragma unroll
    for (int half = 0; half < 2; half++) {
        const int iA = row0 + w * 4 + half * 2;
        const int iB = iA + 1;
        int keyA[DP1], keyB[DP1];
#pragma unroll
        for (int j = 0; j < DP1; j++) {
            keyA[j] = __ldg(&g_qkey[iA * DP1 + j]);
            keyB[j] = __ldg(&g_qkey[iB * DP1 + j]);
        }
        bool vA[DP1], vB[DP1];
        int rwA[DP1], rwB[DP1];
        float ivA[DP1], ivB[DP1];
        float cntA = 0.f, cntB = 0.f;
#pragma unroll
        for (int j = 0; j < DP1; j++) {
            vA[j] = keyA[j] >= 0;  int kA = vA[j] ? keyA[j] : ~keyA[j];
            vB[j] = keyB[j] >= 0;  int kB = vB[j] ? keyB[j] : ~keyB[j];
            rwA[j] = kA >> 4;      ivA[j] = __fdividef(1.f, (float)((kA & 15) + 1));
            rwB[j] = kB >> 4;      ivB[j] = __fdividef(1.f, (float)((kB & 15) + 1));
            cntA += vA[j] ? 1.f : 0.f;
            cntB += vB[j] ? 1.f : 0.f;
        }
        uint2 rA[DP1], rB[DP1];
#pragma unroll
        for (int j = 0; j < DP1; j++) {
            rA[j] = *(const uint2*)&g_prefh[(size_t)rwA[j] * HID + lane * 4];
            rB[j] = *(const uint2*)&g_prefh[(size_t)rwB[j] * HID + lane * 4];
        }
        {
            float4 acc = make_float4(0.f, 0.f, 0.f, 0.f);
#pragma unroll
            for (int j = 0; j < DP1; j++) {
                const float2 a0 = __half22float2(*(__half2*)&rA[j].x);
                const float2 a1 = __half22float2(*(__half2*)&rA[j].y);
                const float iv = ivA[j];
                acc.x += vA[j] ? fmaxf(fmaf(a0.x * iv, sc4.x, sp4.x), 0.f) : 0.f;
                acc.y += vA[j] ? fmaxf(fmaf(a0.y * iv, sc4.y, sp4.y), 0.f) : 0.f;
                acc.z += vA[j] ? fmaxf(fmaf(a1.x * iv, sc4.z, sp4.z), 0.f) : 0.f;
                acc.w += vA[j] ? fmaxf(fmaf(a1.y * iv, sc4.w, sp4.w), 0.f) : 0.f;
            }
            const float inv = __fdividef(1.f, cntA);
            *(float4*)&sA[(w * 4 + half * 2) * HID + lane * 4] =
                make_float4(acc.x * inv, acc.y * inv, acc.z * inv, acc.w * inv);
        }
        {
            float4 acc = make_float4(0.f, 0.f, 0.f, 0.f);
#pragma unroll
            for (int j = 0; j < DP1; j++) {
                const float2 a0 = __half22float2(*(__half2*)&rB[j].x);
                const float2 a1 = __half22float2(*(__half2*)&rB[j].y);
                const float iv = ivB[j];
                acc.x += vB[j] ? fmaxf(fmaf(a0.x * iv, sc4.x, sp4.x), 0.f) : 0.f;
                acc.y += vB[j] ? fmaxf(fmaf(a0.y * iv, sc4.y, sp4.y), 0.f) : 0.f;
                acc.z += vB[j] ? fmaxf(fmaf(a1.x * iv, sc4.z, sp4.z), 0.f) : 0.f;
                acc.w += vB[j] ? fmaxf(fmaf(a1.y * iv, sc4.w, sp4.w), 0.f) : 0.f;
            }
            const float inv = __fdividef(1.f, cntB);
            *(float4*)&sA[(w * 4 + half * 2 + 1) * HID + lane * 4] =
                make_float4(acc.x * inv, acc.y * inv, acc.z * inv, acc.w * inv);
        }
    }
    __syncthreads();
    const int tr = tid >> 4;
    const int tc = tid & 15;
    float acc[2][4];
#pragma unroll
    for (int r = 0; r < 2; r++)
#pragma unroll
        for (int cc = 0; cc < 4; cc++) acc[r][cc] = 0.f;
#pragma unroll 8
    for (int f = 0; f < HID; f++) {
        const float4 wv = *(const float4*)&sW[f * OUT_F + tc * 4];
#pragma unroll
        for (int r = 0; r < 2; r++) {
            const float a = sA[(tr * 2 + r) * HID + f];
            acc[r][0] = fmaf(a, wv.x, acc[r][0]);
            acc[r][1] = fmaf(a, wv.y, acc[r][1]);
            acc[r][2] = fmaf(a, wv.z, acc[r][2]);
            acc[r][3] = fmaf(a, wv.w, acc[r][3]);
        }
    }
    const float4 bbv = *(const float4*)&b2[tc * 4];
    float ps[4] = {0.f, 0.f, 0.f, 0.f}, pq[4] = {0.f, 0.f, 0.f, 0.f};
#pragma unroll
    for (int r = 0; r < 2; r++) {
        float4 o = make_float4(acc[r][0] + bbv.x, acc[r][1] + bbv.y,
                               acc[r][2] + bbv.z, acc[r][3] + bbv.w);
        union { __half2 h[2]; uint2 u; } pk;
        pk.h[0] = __floats2half2_rn(o.x, o.y);
        pk.h[1] = __floats2half2_rn(o.z, o.w);
        *(uint2*)&g_pre2h[(size_t)(row0 + tr * 2 + r) * OUT_F + tc * 4] = pk.u;
        ps[0] += o.x; ps[1] += o.y; ps[2] += o.z; ps[3] += o.w;
        pq[0] += o.x * o.x; pq[1] += o.y * o.y; pq[2] += o.z * o.z; pq[3] += o.w * o.w;
    }
    __syncthreads();                       // everyone done reading sA
    *(float4*)&sA[tr * OUT_F + tc * 4]              = make_float4(ps[0], ps[1], ps[2], ps[3]);
    *(float4*)&sA[16 * OUT_F + tr * OUT_F + tc * 4] = make_float4(pq[0], pq[1], pq[2], pq[3]);
    __syncthreads();
    if (tid < OUT_F) {
        float s = 0.f, q = 0.f;
#pragma unroll
        for (int k = 0; k < 16; k++) {
            s += sA[k * OUT_F + tid];
            q += sA[16 * OUT_F + k * OUT_F + tid];
        }
        atomicAdd(&g_s2[tid * SPAD], s);
        atomicAdd(&g_q2[tid * SPAD], q);
    }
}

// ---------------- K5: decoder + BCE with fused BN2+ReLU (fp16 pre2 rows) ----------------
// 256 thr = 8 warps; 4 pairs/warp (8-lane groups); 1 LDG.128 per side per lane.
__global__ void k_loss(const int* __restrict__ target, const int* __restrict__ neg,
                       const float* __restrict__ g2, const float* __restrict__ be2,
                       const float* __restrict__ Wd, const float* __restrict__ bd,
                       float* __restrict__ out) {
    __shared__ float  sWd[OUT_F], sSc[OUT_F], sSh[OUT_F];
    __shared__ double sAcc[8];
    const int tid = threadIdx.x, w = tid >> 5, lane = tid & 31;
    const int grp = lane >> 3, hl = lane & 7;
    if (tid < OUT_F) {
        sWd[tid] = Wd[tid];
        const float mean = g_s2[tid * SPAD] * (1.f / (float)N_NODES);
        const float var  = g_q2[tid * SPAD] * (1.f / (float)N_NODES) - mean * mean;
        const float sc   = __ldg(&g2[tid]) * rsqrtf(fmaxf(var, 0.f) + EPS);
        sSc[tid] = sc;
        sSh[tid] = __ldg(&be2[tid]) - mean * sc;
    }
    __syncthreads();
    const float bdv = __ldg(&bd[0]);
    const float4 wd0  = *(const float4*)&sWd[hl * 8];
    const float4 wd1  = *(const float4*)&sWd[hl * 8 + 4];
    const float4 sca  = *(const float4*)&sSc[hl * 8];
    const float4 scb  = *(const float4*)&sSc[hl * 8 + 4];
    const float4 sha  = *(const float4*)&sSh[hl * 8];
    const float4 shb  = *(const float4*)&sSh[hl * 8 + 4];
    double acc = 0.0;
    const int p0 = blockIdx.x * 256;
    for (int it = 0; it < 8; it++) {
        const int p = p0 + it * 32 + w * 4 + grp;
        float d = 0.f; float label = 0.f; bool live = (p < 2 * NE);
        if (live) {
            int a, b;
            if (p < NE) { a = __ldg(&target[p]);   b = __ldg(&target[NE + p]); label = 1.f; }
            else        { a = __ldg(&neg[p - NE]); b = __ldg(&neg[p]);         label = 0.f; }
            const uint4 ua = *(const uint4*)&g_pre2h[(size_t)a * OUT_F + hl * 8];
            const uint4 ub = *(const uint4*)&g_pre2h[(size_t)b * OUT_F + hl * 8];
            const float2 a0 = __half22float2(*(__half2*)&ua.x);
            const float2 a1 = __half22float2(*(__half2*)&ua.y);
            const float2 a2 = __half22float2(*(__half2*)&ua.z);
            const float2 a3 = __half22float2(*(__half2*)&ua.w);
            const float2 b0 = __half22float2(*(__half2*)&ub.x);
            const float2 b1v = __half22float2(*(__half2*)&ub.y);
            const float2 b2v = __half22float2(*(__half2*)&ub.z);
            const float2 b3 = __half22float2(*(__half2*)&ub.w);
            float ea0 = fmaxf(fmaf(a0.x, sca.x, sha.x), 0.f);
            float ea1 = fmaxf(fmaf(a0.y, sca.y, sha.y), 0.f);
            float ea2 = fmaxf(fmaf(a1.x, sca.z, sha.z), 0.f);
            float ea3 = fmaxf(fmaf(a1.y, sca.w, sha.w), 0.f);
            float ea4 = fmaxf(fmaf(a2.x, scb.x, shb.x), 0.f);
            float ea5 = fmaxf(fmaf(a2.y, scb.y, shb.y), 0.f);
            float ea6 = fmaxf(fmaf(a3.x, scb.z, shb.z), 0.f);
            float ea7 = fmaxf(fmaf(a3.y, scb.w, shb.w), 0.f);
            float eb0 = fmaxf(fmaf(b0.x, sca.x, sha.x), 0.f);
            float eb1 = fmaxf(fmaf(b0.y, sca.y, sha.y), 0.f);
            float eb2 = fmaxf(fmaf(b1v.x, sca.z, sha.z), 0.f);
            float eb3 = fmaxf(fmaf(b1v.y, sca.w, sha.w), 0.f);
            float eb4 = fmaxf(fmaf(b2v.x, scb.x, shb.x), 0.f);
            float eb5 = fmaxf(fmaf(b2v.y, scb.y, shb.y), 0.f);
            float eb6 = fmaxf(fmaf(b3.x, scb.z, shb.z), 0.f);
            float eb7 = fmaxf(fmaf(b3.y, scb.w, shb.w), 0.f);
            d = ea0 * eb0 * wd0.x;
            d = fmaf(ea1 * eb1, wd0.y, d);
            d = fmaf(ea2 * eb2, wd0.z, d);
            d = fmaf(ea3 * eb3, wd0.w, d);
            d = fmaf(ea4 * eb4, wd1.x, d);
            d = fmaf(ea5 * eb5, wd1.y, d);
            d = fmaf(ea6 * eb6, wd1.z, d);
            d = fmaf(ea7 * eb7, wd1.w, d);
        }
#pragma unroll
        for (int off = 4; off; off >>= 1) d += __shfl_xor_sync(0xffffffff, d, off);
        if (hl == 0 && live) {
            const float pl   = d + bdv;
            const float term = fmaxf(pl, 0.f) - pl * label + log1pf(__expf(-fabsf(pl)));
            acc += (double)term;
        }
    }
    acc += __shfl_xor_sync(0xffffffff, acc, 8);
    acc += __shfl_xor_sync(0xffffffff, acc, 16);
    if (lane == 0) sAcc[w] = acc;
    __syncthreads();
    if (tid == 0) {
        double s = 0.0;
#pragma unroll
        for (int k = 0; k < 8; k++) s += sAcc[k];
        atomicAdd(&g_loss, s);
        __threadfence();
        const int dn = atomicAdd(&g_done, 1);
        if (dn == (int)gridDim.x - 1)
            out[0] = (float)(g_loss * (1.0 / (2.0 * (double)NE)));
    }
}

// ---------------- launch ----------------
extern "C" void kernel_launch(void* const* d_in, const int* in_sizes, int n_in,
                              void* d_out, int out_size) {
    const float* x       = (const float*)d_in[0];
    const float* node_ts = (const float*)d_in[1];
    const int*   nbi     = (const int*)  d_in[2];
    const float* nbt     = (const float*)d_in[3];
    const int*   target  = (const int*)  d_in[4];
    const int*   neg     = (const int*)  d_in[5];
    const float* W1      = (const float*)d_in[6];
    const float* b1      = (const float*)d_in[7];
    const float* g1      = (const float*)d_in[8];
    const float* be1     = (const float*)d_in[9];
    const float* W2      = (const float*)d_in[10];
    const float* b2      = (const float*)d_in[11];
    const float* g2      = (const float*)d_in[12];
    const float* be2     = (const float*)d_in[13];
    const float* Wd      = (const float*)d_in[14];
    const float* bd      = (const float*)d_in[15];
    float* out = (float*)d_out;

    k_gemm1  <<<N_NODES / 32, 128>>>(x, W1, nbi, nbt);
    k_widx   <<<(M_ROWS + 255) / 256, 256>>>(node_ts, nbi, nbt);
    k_pref   <<<N_NODES / 8, 256>>>(b1);
    k_bngemm2<<<N_NODES / 32, 256>>>(g1, be1, b1, W2, b2);        // <- profiled (4th)
    k_loss   <<<(2 * NE + 255) / 256, 256>>>(target, neg, g2, be2, Wd, bd, out);
}